// round 1
// baseline (speedup 1.0000x reference)
#include <cuda_runtime.h>
#include <math.h>

#define TSEQ 256
#define CDIM 384
#define HDIM 64
#define CK   32
#define NCHUNK 12          // CDIM / CK
#define SXLD 33            // padded row stride for x chunk (bank-conflict-free)

// One projection pass: acc[t][0:64] = x_b[t, :] @ W  (thread t owns row t)
__device__ __forceinline__ void project_pass(
    const float* __restrict__ gx, const float* __restrict__ gw,
    float* __restrict__ sX, float4* __restrict__ sW4,
    float acc[HDIM], int tid)
{
#pragma unroll
    for (int h = 0; h < HDIM; ++h) acc[h] = 0.f;

    for (int ch = 0; ch < NCHUNK; ++ch) {
        __syncthreads();   // protect previous chunk's consumers
        // ---- load x chunk [256][32] as 2048 float4 (coalesced), store padded ----
#pragma unroll
        for (int j = 0; j < 8; ++j) {
            int idx = tid + j * 256;
            int t   = idx >> 3;
            int c4  = (idx & 7) << 2;
            float4 v = *reinterpret_cast<const float4*>(gx + t * CDIM + ch * CK + c4);
            float* d = sX + t * SXLD + c4;
            d[0] = v.x; d[1] = v.y; d[2] = v.z; d[3] = v.w;
        }
        // ---- load W chunk [32][64] as 512 float4 (coalesced) ----
#pragma unroll
        for (int j = 0; j < 2; ++j) {
            int idx = tid + j * 256;
            int r   = idx >> 4;
            int h4  = idx & 15;
            sW4[idx] = *reinterpret_cast<const float4*>(gw + (ch * CK + r) * HDIM + (h4 << 2));
        }
        __syncthreads();
        // ---- accumulate: 2048 FFMA + 512 LDS.128 + 32 LDS.32 per thread ----
        const float* xr = sX + tid * SXLD;
#pragma unroll 8
        for (int cc = 0; cc < CK; ++cc) {
            float xv = xr[cc];
            const float4* wr = sW4 + cc * 16;
#pragma unroll
            for (int h4 = 0; h4 < 16; ++h4) {
                float4 w = wr[h4];
                acc[h4*4+0] = fmaf(xv, w.x, acc[h4*4+0]);
                acc[h4*4+1] = fmaf(xv, w.y, acc[h4*4+1]);
                acc[h4*4+2] = fmaf(xv, w.z, acc[h4*4+2]);
                acc[h4*4+3] = fmaf(xv, w.w, acc[h4*4+3]);
            }
        }
    }
}

__global__ void __launch_bounds__(256, 1)
head_kernel(const float* __restrict__ x, const float* __restrict__ Wq,
            const float* __restrict__ Wk, const float* __restrict__ Wv,
            float* __restrict__ out)
{
    extern __shared__ float smem[];
    float*  sK  = smem;                                   // 256*64 = 16384 f
    float*  sV  = sK + TSEQ * HDIM;                       // 256*64 = 16384 f
    float*  sX  = sV + TSEQ * HDIM;                       // 256*33 =  8448 f
    float4* sW4 = reinterpret_cast<float4*>(sX + TSEQ * SXLD);  // 32*64 = 2048 f

    const int tid = threadIdx.x;                          // == row t (T=256)
    const float* gx = x + (size_t)blockIdx.x * (TSEQ * CDIM);

    float acc[HDIM];

    // ---- Phase 1: K pass -> smem ----
    project_pass(gx, Wk, sX, sW4, acc, tid);
    {
        float4* dst = reinterpret_cast<float4*>(sK + tid * HDIM);
#pragma unroll
        for (int h4 = 0; h4 < 16; ++h4)
            dst[h4] = make_float4(acc[h4*4], acc[h4*4+1], acc[h4*4+2], acc[h4*4+3]);
    }
    // ---- V pass -> smem ----
    project_pass(gx, Wv, sX, sW4, acc, tid);
    {
        float4* dst = reinterpret_cast<float4*>(sV + tid * HDIM);
#pragma unroll
        for (int h4 = 0; h4 < 16; ++h4)
            dst[h4] = make_float4(acc[h4*4], acc[h4*4+1], acc[h4*4+2], acc[h4*4+3]);
    }
    // ---- Q pass -> registers (acc) ----
    project_pass(gx, Wq, sX, sW4, acc, tid);
    __syncthreads();   // sK/sV stores visible to all threads

    // fold 1/sqrt(C) and log2(e) into q so logits are in exp2 domain
    const float scale = 1.44269504088896340736f * rsqrtf((float)CDIM);
#pragma unroll
    for (int h = 0; h < HDIM; ++h) acc[h] *= scale;

    // ---- Phase 2: online-softmax causal attention, thread t = query row t ----
    float o[HDIM];
#pragma unroll
    for (int h = 0; h < HDIM; ++h) o[h] = 0.f;
    float m = -INFINITY, l = 0.f;

    const float4* K4 = reinterpret_cast<const float4*>(sK);
    const float4* V4 = reinterpret_cast<const float4*>(sV);

    for (int s = 0; s <= tid; ++s) {
        float s0 = 0.f, s1 = 0.f, s2 = 0.f, s3 = 0.f;
#pragma unroll
        for (int h4 = 0; h4 < 16; ++h4) {
            float4 kv = K4[s * 16 + h4];                  // warp-broadcast
            s0 = fmaf(acc[h4*4+0], kv.x, s0);
            s1 = fmaf(acc[h4*4+1], kv.y, s1);
            s2 = fmaf(acc[h4*4+2], kv.z, s2);
            s3 = fmaf(acc[h4*4+3], kv.w, s3);
        }
        float sc = (s0 + s1) + (s2 + s3);                 // log2-domain logit

        if (sc > m) {                                     // rare after warmup
            float alpha = exp2f(m - sc);                  // m=-inf -> 0, safe
            m = sc;
            l = fmaf(l, alpha, 1.f);
#pragma unroll
            for (int h4 = 0; h4 < 16; ++h4) {
                float4 vv = V4[s * 16 + h4];
                o[h4*4+0] = fmaf(o[h4*4+0], alpha, vv.x);
                o[h4*4+1] = fmaf(o[h4*4+1], alpha, vv.y);
                o[h4*4+2] = fmaf(o[h4*4+2], alpha, vv.z);
                o[h4*4+3] = fmaf(o[h4*4+3], alpha, vv.w);
            }
        } else {
            float p = exp2f(sc - m);
            l += p;
#pragma unroll
            for (int h4 = 0; h4 < 16; ++h4) {
                float4 vv = V4[s * 16 + h4];
                o[h4*4+0] = fmaf(p, vv.x, o[h4*4+0]);
                o[h4*4+1] = fmaf(p, vv.y, o[h4*4+1]);
                o[h4*4+2] = fmaf(p, vv.z, o[h4*4+2]);
                o[h4*4+3] = fmaf(p, vv.w, o[h4*4+3]);
            }
        }
    }

    float inv = 1.f / l;
    float4* go = reinterpret_cast<float4*>(out + ((size_t)blockIdx.x * TSEQ + tid) * HDIM);
#pragma unroll
    for (int h4 = 0; h4 < 16; ++h4)
        go[h4] = make_float4(o[h4*4+0] * inv, o[h4*4+1] * inv,
                             o[h4*4+2] * inv, o[h4*4+3] * inv);
}

extern "C" void kernel_launch(void* const* d_in, const int* in_sizes, int n_in,
                              void* d_out, int out_size)
{
    const float* x  = (const float*)d_in[0];
    const float* Wq = (const float*)d_in[1];
    const float* Wk = (const float*)d_in[2];
    const float* Wv = (const float*)d_in[3];
    float* out = (float*)d_out;

    int B = in_sizes[0] / (TSEQ * CDIM);   // 1024

    size_t smem_bytes = (size_t)(TSEQ * HDIM * 2 + TSEQ * SXLD + CK * HDIM) * sizeof(float);
    cudaFuncSetAttribute(head_kernel, cudaFuncAttributeMaxDynamicSharedMemorySize,
                         (int)smem_bytes);
    head_kernel<<<B, 256, smem_bytes>>>(x, Wq, Wk, Wv, out);
}

// round 7
// speedup vs baseline: 3.1071x; 3.1071x over previous
#include <cuda_runtime.h>
#include <cuda_bf16.h>
#include <math.h>
#include <stdint.h>

#define BATCH 1024
#define TSEQ  256
#define CDIM  384
#define HDIM  64
#define NDIM  192
#define KC    64

// ---- global scratch: QKV as bf16 hi/lo --------------------------------------
__device__ __align__(16) __nv_bfloat16 g_hi[(size_t)BATCH * TSEQ * NDIM];
__device__ __align__(16) __nv_bfloat16 g_lo[(size_t)BATCH * TSEQ * NDIM];

// ---- helpers ----------------------------------------------------------------
__device__ __forceinline__ uint32_t smem_u32(const void* p) {
    uint32_t a;
    asm("{ .reg .u64 t; cvta.to.shared.u64 t, %1; cvt.u32.u64 %0, t; }" : "=r"(a) : "l"(p));
    return a;
}
// 128B-row tile swizzle (8 16B atoms per row)
__device__ __forceinline__ int swz128(int row, int byteoff) {
    return row * 128 + ((((byteoff >> 4) ^ row) & 7) << 4) + (byteoff & 15);
}
// W tile: 384B rows (24 atoms), swizzle within 8-atom groups
__device__ __forceinline__ int swzW(int k, int byteoff) {
    int atom = byteoff >> 4;
    return k * 384 + (((atom & ~7) | ((atom ^ k) & 7)) << 4) + (byteoff & 15);
}
__device__ __forceinline__ uint32_t pk(float lo, float hi) {   // bf16x2 {hi|lo}
    uint32_t r; asm("cvt.rn.bf16x2.f32 %0, %1, %2;" : "=r"(r) : "f"(hi), "f"(lo)); return r;
}
__device__ __forceinline__ float2 upk(uint32_t v) {            // exact bf16->f32
    float2 f;
    f.x = __uint_as_float(v << 16);
    f.y = __uint_as_float(v & 0xFFFF0000u);
    return f;
}
__device__ __forceinline__ float ex2(float x) {
    float y; asm("ex2.approx.ftz.f32 %0, %1;" : "=f"(y) : "f"(x)); return y;
}
__device__ __forceinline__ void ldsm4(uint32_t* r, uint32_t a) {
    asm volatile("ldmatrix.sync.aligned.m8n8.x4.shared.b16 {%0,%1,%2,%3}, [%4];"
                 : "=r"(r[0]), "=r"(r[1]), "=r"(r[2]), "=r"(r[3]) : "r"(a));
}
__device__ __forceinline__ void ldsm2(uint32_t& r0, uint32_t& r1, uint32_t a) {
    asm volatile("ldmatrix.sync.aligned.m8n8.x2.shared.b16 {%0,%1}, [%2];"
                 : "=r"(r0), "=r"(r1) : "r"(a));
}
__device__ __forceinline__ void ldsm2t(uint32_t& r0, uint32_t& r1, uint32_t a) {
    asm volatile("ldmatrix.sync.aligned.m8n8.x2.trans.shared.b16 {%0,%1}, [%2];"
                 : "=r"(r0), "=r"(r1) : "r"(a));
}
__device__ __forceinline__ void mma16816(float* c, const uint32_t* a,
                                         uint32_t b0, uint32_t b1) {
    asm volatile("mma.sync.aligned.m16n8k16.row.col.f32.bf16.bf16.f32 "
                 "{%0,%1,%2,%3}, {%4,%5,%6,%7}, {%8,%9}, {%0,%1,%2,%3};"
                 : "+f"(c[0]), "+f"(c[1]), "+f"(c[2]), "+f"(c[3])
                 : "r"(a[0]), "r"(a[1]), "r"(a[2]), "r"(a[3]), "r"(b0), "r"(b1));
}

// ============================================================================
// Kernel 1: QKV projection.  grid=2048 (M-tiles of 128), 256 thr.
// Warp w owns rows 16w..16w+15 of the tile; acc[24][4] covers N=192.
// ============================================================================
#define PX_HI 0
#define PX_LO 16384
#define PW_HI 32768
#define PW_LO 57344
#define PSMEM 81920

__global__ void __launch_bounds__(256, 1)
proj_kernel(const float* __restrict__ x, const float* __restrict__ Wq,
            const float* __restrict__ Wk, const float* __restrict__ Wv)
{
    extern __shared__ char sm[];
    const uint32_t smb = smem_u32(sm);
    const int tid = threadIdx.x, lane = tid & 31, w = tid >> 5;
    const int g = lane >> 2, t2 = (lane & 3) << 1;
    const float* gx = x + (size_t)blockIdx.x * 128 * CDIM;

    float acc[24][4];
#pragma unroll
    for (int nt = 0; nt < 24; ++nt)
#pragma unroll
        for (int i = 0; i < 4; ++i) acc[nt][i] = 0.f;

    for (int ch = 0; ch < 6; ++ch) {
        const int kc = ch * KC;
        __syncthreads();
        // stage X chunk [128m x 64k] -> bf16 hi/lo swizzled
#pragma unroll
        for (int i = 0; i < 8; ++i) {
            int idx = tid + (i << 8);
            int row = idx >> 4, f4 = idx & 15;
            float4 v = *reinterpret_cast<const float4*>(gx + row * CDIM + kc + (f4 << 2));
            uint32_t h0 = pk(v.x, v.y), h1 = pk(v.z, v.w);
            float2 u0 = upk(h0), u1 = upk(h1);
            uint32_t l0 = pk(v.x - u0.x, v.y - u0.y);
            uint32_t l1 = pk(v.z - u1.x, v.w - u1.y);
            int off = swz128(row, 8 * f4);
            *reinterpret_cast<uint2*>(sm + PX_HI + off) = make_uint2(h0, h1);
            *reinterpret_cast<uint2*>(sm + PX_LO + off) = make_uint2(l0, l1);
        }
        // stage W chunk [64k x 192n] hi + lo
#pragma unroll
        for (int i = 0; i < 12; ++i) {
            int idx = tid + (i << 8);
            int k = idx / 48, f4 = idx % 48;
            int n0 = f4 << 2;
            const float* Wp = (n0 < 64) ? Wq : (n0 < 128) ? Wk : Wv;
            float4 v = *reinterpret_cast<const float4*>(Wp + (kc + k) * HDIM + (n0 & 63));
            uint32_t h0 = pk(v.x, v.y), h1 = pk(v.z, v.w);
            float2 u0 = upk(h0), u1 = upk(h1);
            int off = swzW(k, 2 * n0);
            *reinterpret_cast<uint2*>(sm + PW_HI + off) = make_uint2(h0, h1);
            *reinterpret_cast<uint2*>(sm + PW_LO + off) =
                make_uint2(pk(v.x - u0.x, v.y - u0.y), pk(v.z - u1.x, v.w - u1.y));
        }
        __syncthreads();
        // chains: Ahi*Whi + Alo*Whi + Ahi*Wlo (lo*lo dropped)
        for (int ks = 0; ks < 4; ++ks) {
            uint32_t ah[4], al[4];
            int arow  = (w << 4) + (lane & 15);
            int abyte = ((ks << 1) + (lane >> 4)) << 4;
            ldsm4(ah, smb + PX_HI + swz128(arow, abyte));
            ldsm4(al, smb + PX_LO + swz128(arow, abyte));
            int krow = (ks << 4) + (lane & 15);
#pragma unroll
            for (int nt = 0; nt < 24; ++nt) {
                uint32_t b0, b1;
                ldsm2t(b0, b1, smb + PW_HI + swzW(krow, nt << 4));
                mma16816(acc[nt], ah, b0, b1);
                mma16816(acc[nt], al, b0, b1);
                ldsm2t(b0, b1, smb + PW_LO + swzW(krow, nt << 4));
                mma16816(acc[nt], ah, b0, b1);
            }
        }
    }

    // epilogue: scale Q by eta, re-split hi/lo, store to scratch
    const float eta = 1.44269504088896340736f * rsqrtf((float)CDIM);
    const size_t grow0 = (size_t)blockIdx.x * 128;
#pragma unroll
    for (int nt = 0; nt < 24; ++nt) {
#pragma unroll
        for (int r = 0; r < 2; ++r) {
            float p0 = acc[nt][2 * r], p1 = acc[nt][2 * r + 1];
            if (nt < 8) { p0 *= eta; p1 *= eta; }
            uint32_t hi = pk(p0, p1);
            float2 u = upk(hi);
            uint32_t lo = pk(p0 - u.x, p1 - u.y);
            int row = (w << 4) + g + (r << 3);
            size_t gi = (grow0 + row) * NDIM + (nt << 3) + t2;   // t2 even -> u32 ok
            *reinterpret_cast<uint32_t*>(&g_hi[gi]) = hi;
            *reinterpret_cast<uint32_t*>(&g_lo[gi]) = lo;
        }
    }
}

// ============================================================================
// Kernel 2: causal flash attention.  grid=1024, 256 thr, 192 KB smem.
// ============================================================================
#define AQ_HI 0
#define AQ_LO 32768
#define AK_HI 65536
#define AK_LO 98304
#define AV_HI 131072
#define AV_LO 163840
#define ASMEM 196608

__global__ void __launch_bounds__(256, 1)
attn_kernel(float* __restrict__ out)
{
    extern __shared__ char sm[];
    const uint32_t smb = smem_u32(sm);
    const int tid = threadIdx.x, lane = tid & 31, w = tid >> 5;
    const int g = lane >> 2, t2 = (lane & 3) << 1;
    const size_t base = (size_t)blockIdx.x * TSEQ * NDIM;

    // stage Q/K/V hi/lo -> swizzled smem (coalesced 128B row-sections)
    for (int sec = 0; sec < 3; ++sec) {
#pragma unroll
        for (int i = 0; i < 8; ++i) {
            int idx = tid + (i << 8);
            int row = idx >> 3, a = idx & 7;
            size_t gi = base + (size_t)row * NDIM + sec * 64 + (a << 3);
            uint4 h = *reinterpret_cast<const uint4*>(&g_hi[gi]);
            uint4 l = *reinterpret_cast<const uint4*>(&g_lo[gi]);
            int off = swz128(row, a << 4);
            *reinterpret_cast<uint4*>(sm + sec * 65536 + off) = h;
            *reinterpret_cast<uint4*>(sm + sec * 65536 + 32768 + off) = l;
        }
    }
    __syncthreads();

    float O[2][8][4];
#pragma unroll
    for (int mt = 0; mt < 2; ++mt)
#pragma unroll
        for (int nt = 0; nt < 8; ++nt)
#pragma unroll
            for (int i = 0; i < 4; ++i) O[mt][nt][i] = 0.f;
    float mrow[2][2] = {{-1e30f, -1e30f}, {-1e30f, -1e30f}};
    float lrow[2][2] = {{0.f, 0.f}, {0.f, 0.f}};

    const int jmax = w >> 1;
    for (int jt = 0; jt <= jmax; ++jt) {
        float S[2][8][4];
#pragma unroll
        for (int mt = 0; mt < 2; ++mt)
#pragma unroll
            for (int nt = 0; nt < 8; ++nt)
#pragma unroll
                for (int i = 0; i < 4; ++i) S[mt][nt][i] = 0.f;

        // ---- S = Q K^T (hi*hi + lo*hi + hi*lo) -----------------------------
        for (int ks = 0; ks < 4; ++ks) {
            uint32_t qh[2][4], ql[2][4];
            int arow  = (w << 5) + (lane & 15);
            int abyte = ((ks << 1) + (lane >> 4)) << 4;
            ldsm4(qh[0], smb + AQ_HI + swz128(arow,      abyte));
            ldsm4(qh[1], smb + AQ_HI + swz128(arow + 16, abyte));
            ldsm4(ql[0], smb + AQ_LO + swz128(arow,      abyte));
            ldsm4(ql[1], smb + AQ_LO + swz128(arow + 16, abyte));
            int kr    = (jt << 6) + (lane & 7);
            int kbyte = ((ks << 1) + ((lane >> 3) & 1)) << 4;
#pragma unroll
            for (int nt = 0; nt < 8; ++nt) {
                uint32_t b0, b1;
                ldsm2(b0, b1, smb + AK_HI + swz128(kr + (nt << 3), kbyte));
                mma16816(S[0][nt], qh[0], b0, b1);
                mma16816(S[1][nt], qh[1], b0, b1);
                mma16816(S[0][nt], ql[0], b0, b1);
                mma16816(S[1][nt], ql[1], b0, b1);
                ldsm2(b0, b1, smb + AK_LO + swz128(kr + (nt << 3), kbyte));
                mma16816(S[0][nt], qh[0], b0, b1);
                mma16816(S[1][nt], qh[1], b0, b1);
            }
        }
        // ---- causal mask on diagonal tile ----------------------------------
        if (jt == jmax) {
#pragma unroll
            for (int mt = 0; mt < 2; ++mt)
#pragma unroll
                for (int nt = 0; nt < 8; ++nt)
#pragma unroll
                    for (int r = 0; r < 2; ++r)
#pragma unroll
                        for (int cc = 0; cc < 2; ++cc) {
                            int col = (jt << 6) + (nt << 3) + t2 + cc;
                            int row = (w << 5) + (mt << 4) + g + (r << 3);
                            if (col > row) S[mt][nt][2 * r + cc] = -1e30f;
                        }
        }
        // ---- online softmax -------------------------------------------------
#pragma unroll
        for (int mt = 0; mt < 2; ++mt)
#pragma unroll
            for (int r = 0; r < 2; ++r) {
                float vmax = -1e30f;
#pragma unroll
                for (int nt = 0; nt < 8; ++nt)
                    vmax = fmaxf(vmax, fmaxf(S[mt][nt][2 * r], S[mt][nt][2 * r + 1]));
                vmax = fmaxf(vmax, __shfl_xor_sync(0xffffffffu, vmax, 1));
                vmax = fmaxf(vmax, __shfl_xor_sync(0xffffffffu, vmax, 2));
                float mnew  = fmaxf(mrow[mt][r], vmax);
                float alpha = ex2(mrow[mt][r] - mnew);
                mrow[mt][r] = mnew;
                float ls = 0.f;
#pragma unroll
                for (int nt = 0; nt < 8; ++nt) {
                    float p0 = ex2(S[mt][nt][2 * r]     - mnew);
                    float p1 = ex2(S[mt][nt][2 * r + 1] - mnew);
                    S[mt][nt][2 * r] = p0; S[mt][nt][2 * r + 1] = p1;
                    ls += p0 + p1;
                }
                lrow[mt][r] = lrow[mt][r] * alpha + ls;
#pragma unroll
                for (int nt = 0; nt < 8; ++nt) {
                    O[mt][nt][2 * r]     *= alpha;
                    O[mt][nt][2 * r + 1] *= alpha;
                }
            }
        // ---- O += P V (P hi/lo, V hi/lo; lo*lo dropped) --------------------
#pragma unroll
        for (int ks = 0; ks < 4; ++ks) {            // MUST unroll: S indexed by ks
            uint32_t ph[2][4], pl[2][4];
#pragma unroll
            for (int mt = 0; mt < 2; ++mt) {
                ph[mt][0] = pk(S[mt][2 * ks][0],     S[mt][2 * ks][1]);
                ph[mt][1] = pk(S[mt][2 * ks][2],     S[mt][2 * ks][3]);
                ph[mt][2] = pk(S[mt][2 * ks + 1][0], S[mt][2 * ks + 1][1]);
                ph[mt][3] = pk(S[mt][2 * ks + 1][2], S[mt][2 * ks + 1][3]);
#pragma unroll
                for (int i = 0; i < 4; ++i) {
                    int tnt = 2 * ks + (i >> 1), tr = i & 1;
                    float2 u = upk(ph[mt][i]);
                    pl[mt][i] = pk(S[mt][tnt][2 * tr] - u.x, S[mt][tnt][2 * tr + 1] - u.y);
                }
            }
            int vr = (jt << 6) + (ks << 4) + (lane & 15);
#pragma unroll
            for (int nt = 0; nt < 8; ++nt) {
                uint32_t b0, b1;
                ldsm2t(b0, b1, smb + AV_HI + swz128(vr, nt << 4));
                mma16816(O[0][nt], ph[0], b0, b1);
                mma16816(O[1][nt], ph[1], b0, b1);
                mma16816(O[0][nt], pl[0], b0, b1);
                mma16816(O[1][nt], pl[1], b0, b1);
                ldsm2t(b0, b1, smb + AV_LO + swz128(vr, nt << 4));
                mma16816(O[0][nt], ph[0], b0, b1);
                mma16816(O[1][nt], ph[1], b0, b1);
            }
        }
    }

    // finalize + store
#pragma unroll
    for (int mt = 0; mt < 2; ++mt)
#pragma unroll
        for (int r = 0; r < 2; ++r) {
            float lt = lrow[mt][r];
            lt += __shfl_xor_sync(0xffffffffu, lt, 1);
            lt += __shfl_xor_sync(0xffffffffu, lt, 2);
            float inv = __frcp_rn(lt);
            int row = (w << 5) + (mt << 4) + g + (r << 3);
            float* op = out + ((size_t)blockIdx.x * TSEQ + row) * HDIM;
#pragma unroll
            for (int nt = 0; nt < 8; ++nt) {
                float2 v = make_float2(O[mt][nt][2 * r] * inv, O[mt][nt][2 * r + 1] * inv);
                *reinterpret_cast<float2*>(op + (nt << 3) + t2) = v;
            }
        }
}

// ---- launch -----------------------------------------------------------------
extern "C" void kernel_launch(void* const* d_in, const int* in_sizes, int n_in,
                              void* d_out, int out_size)
{
    const float* x  = (const float*)d_in[0];
    const float* Wq = (const float*)d_in[1];
    const float* Wk = (const float*)d_in[2];
    const float* Wv = (const float*)d_in[3];
    float* out = (float*)d_out;

    int B = in_sizes[0] / (TSEQ * CDIM);          // 1024
    int Mtiles = (B * TSEQ) / 128;                // 2048

    cudaFuncSetAttribute(proj_kernel, cudaFuncAttributeMaxDynamicSharedMemorySize, PSMEM);
    cudaFuncSetAttribute(attn_kernel, cudaFuncAttributeMaxDynamicSharedMemorySize, ASMEM);

    proj_kernel<<<Mtiles, 256, PSMEM>>>(x, Wq, Wk, Wv);
    attn_kernel<<<B, 256, ASMEM>>>(out);
}

// round 8
// speedup vs baseline: 3.1111x; 1.0013x over previous
#include <cuda_runtime.h>
#include <cuda_bf16.h>
#include <math.h>
#include <stdint.h>

#define BATCH 1024
#define TSEQ  256
#define CDIM  384
#define HDIM  64
#define NDIM  192
#define KC    64

// ---- global scratch: QKV as bf16 hi/lo --------------------------------------
__device__ __align__(16) __nv_bfloat16 g_hi[(size_t)BATCH * TSEQ * NDIM];
__device__ __align__(16) __nv_bfloat16 g_lo[(size_t)BATCH * TSEQ * NDIM];

// ---- helpers ----------------------------------------------------------------
__device__ __forceinline__ uint32_t smem_u32(const void* p) {
    uint32_t a;
    asm("{ .reg .u64 t; cvta.to.shared.u64 t, %1; cvt.u32.u64 %0, t; }" : "=r"(a) : "l"(p));
    return a;
}
// 128B-row tile swizzle (8 16B atoms per row)
__device__ __forceinline__ int swz128(int row, int byteoff) {
    return row * 128 + ((((byteoff >> 4) ^ row) & 7) << 4) + (byteoff & 15);
}
// W tile: 384B rows (24 atoms), swizzle within 8-atom groups
__device__ __forceinline__ int swzW(int k, int byteoff) {
    int atom = byteoff >> 4;
    return k * 384 + (((atom & ~7) | ((atom ^ k) & 7)) << 4) + (byteoff & 15);
}
__device__ __forceinline__ uint32_t pk(float lo, float hi) {   // bf16x2 {hi|lo}
    uint32_t r; asm("cvt.rn.bf16x2.f32 %0, %1, %2;" : "=r"(r) : "f"(hi), "f"(lo)); return r;
}
__device__ __forceinline__ float2 upk(uint32_t v) {            // exact bf16->f32
    float2 f;
    f.x = __uint_as_float(v << 16);
    f.y = __uint_as_float(v & 0xFFFF0000u);
    return f;
}
__device__ __forceinline__ float ex2(float x) {
    float y; asm("ex2.approx.ftz.f32 %0, %1;" : "=f"(y) : "f"(x)); return y;
}
__device__ __forceinline__ void ldsm4(uint32_t* r, uint32_t a) {
    asm volatile("ldmatrix.sync.aligned.m8n8.x4.shared.b16 {%0,%1,%2,%3}, [%4];"
                 : "=r"(r[0]), "=r"(r[1]), "=r"(r[2]), "=r"(r[3]) : "r"(a));
}
__device__ __forceinline__ void ldsm2(uint32_t& r0, uint32_t& r1, uint32_t a) {
    asm volatile("ldmatrix.sync.aligned.m8n8.x2.shared.b16 {%0,%1}, [%2];"
                 : "=r"(r0), "=r"(r1) : "r"(a));
}
__device__ __forceinline__ void ldsm2t(uint32_t& r0, uint32_t& r1, uint32_t a) {
    asm volatile("ldmatrix.sync.aligned.m8n8.x2.trans.shared.b16 {%0,%1}, [%2];"
                 : "=r"(r0), "=r"(r1) : "r"(a));
}
__device__ __forceinline__ void mma16816(float* c, const uint32_t* a,
                                         uint32_t b0, uint32_t b1) {
    asm volatile("mma.sync.aligned.m16n8k16.row.col.f32.bf16.bf16.f32 "
                 "{%0,%1,%2,%3}, {%4,%5,%6,%7}, {%8,%9}, {%0,%1,%2,%3};"
                 : "+f"(c[0]), "+f"(c[1]), "+f"(c[2]), "+f"(c[3])
                 : "r"(a[0]), "r"(a[1]), "r"(a[2]), "r"(a[3]), "r"(b0), "r"(b1));
}

// ============================================================================
// Kernel 1: QKV projection.  grid=2048 (M-tiles of 128), 256 thr.
// Warp w owns rows 16w..16w+15 of the tile; acc[24][4] covers N=192.
// ============================================================================
#define PX_HI 0
#define PX_LO 16384
#define PW_HI 32768
#define PW_LO 57344
#define PSMEM 81920

__global__ void __launch_bounds__(256, 1)
proj_kernel(const float* __restrict__ x, const float* __restrict__ Wq,
            const float* __restrict__ Wk, const float* __restrict__ Wv)
{
    extern __shared__ char sm[];
    const uint32_t smb = smem_u32(sm);
    const int tid = threadIdx.x, lane = tid & 31, w = tid >> 5;
    const int g = lane >> 2, t2 = (lane & 3) << 1;
    const float* gx = x + (size_t)blockIdx.x * 128 * CDIM;

    float acc[24][4];
#pragma unroll
    for (int nt = 0; nt < 24; ++nt)
#pragma unroll
        for (int i = 0; i < 4; ++i) acc[nt][i] = 0.f;

    for (int ch = 0; ch < 6; ++ch) {
        const int kc = ch * KC;
        __syncthreads();
        // stage X chunk [128m x 64k] -> bf16 hi/lo swizzled
#pragma unroll
        for (int i = 0; i < 8; ++i) {
            int idx = tid + (i << 8);
            int row = idx >> 4, f4 = idx & 15;
            float4 v = *reinterpret_cast<const float4*>(gx + row * CDIM + kc + (f4 << 2));
            uint32_t h0 = pk(v.x, v.y), h1 = pk(v.z, v.w);
            float2 u0 = upk(h0), u1 = upk(h1);
            uint32_t l0 = pk(v.x - u0.x, v.y - u0.y);
            uint32_t l1 = pk(v.z - u1.x, v.w - u1.y);
            int off = swz128(row, 8 * f4);
            *reinterpret_cast<uint2*>(sm + PX_HI + off) = make_uint2(h0, h1);
            *reinterpret_cast<uint2*>(sm + PX_LO + off) = make_uint2(l0, l1);
        }
        // stage W chunk [64k x 192n] hi + lo
#pragma unroll
        for (int i = 0; i < 12; ++i) {
            int idx = tid + (i << 8);
            int k = idx / 48, f4 = idx % 48;
            int n0 = f4 << 2;
            const float* Wp = (n0 < 64) ? Wq : (n0 < 128) ? Wk : Wv;
            float4 v = *reinterpret_cast<const float4*>(Wp + (kc + k) * HDIM + (n0 & 63));
            uint32_t h0 = pk(v.x, v.y), h1 = pk(v.z, v.w);
            float2 u0 = upk(h0), u1 = upk(h1);
            int off = swzW(k, 2 * n0);
            *reinterpret_cast<uint2*>(sm + PW_HI + off) = make_uint2(h0, h1);
            *reinterpret_cast<uint2*>(sm + PW_LO + off) =
                make_uint2(pk(v.x - u0.x, v.y - u0.y), pk(v.z - u1.x, v.w - u1.y));
        }
        __syncthreads();
        // chains: Ahi*Whi + Alo*Whi + Ahi*Wlo (lo*lo dropped)
        for (int ks = 0; ks < 4; ++ks) {
            uint32_t ah[4], al[4];
            int arow  = (w << 4) + (lane & 15);
            int abyte = ((ks << 1) + (lane >> 4)) << 4;
            ldsm4(ah, smb + PX_HI + swz128(arow, abyte));
            ldsm4(al, smb + PX_LO + swz128(arow, abyte));
            int krow = (ks << 4) + (lane & 15);
#pragma unroll
            for (int nt = 0; nt < 24; ++nt) {
                uint32_t b0, b1;
                ldsm2t(b0, b1, smb + PW_HI + swzW(krow, nt << 4));
                mma16816(acc[nt], ah, b0, b1);
                mma16816(acc[nt], al, b0, b1);
                ldsm2t(b0, b1, smb + PW_LO + swzW(krow, nt << 4));
                mma16816(acc[nt], ah, b0, b1);
            }
        }
    }

    // epilogue: scale Q by eta, re-split hi/lo, store to scratch
    const float eta = 1.44269504088896340736f * rsqrtf((float)CDIM);
    const size_t grow0 = (size_t)blockIdx.x * 128;
#pragma unroll
    for (int nt = 0; nt < 24; ++nt) {
#pragma unroll
        for (int r = 0; r < 2; ++r) {
            float p0 = acc[nt][2 * r], p1 = acc[nt][2 * r + 1];
            if (nt < 8) { p0 *= eta; p1 *= eta; }
            uint32_t hi = pk(p0, p1);
            float2 u = upk(hi);
            uint32_t lo = pk(p0 - u.x, p1 - u.y);
            int row = (w << 4) + g + (r << 3);
            size_t gi = (grow0 + row) * NDIM + (nt << 3) + t2;   // t2 even -> u32 ok
            *reinterpret_cast<uint32_t*>(&g_hi[gi]) = hi;
            *reinterpret_cast<uint32_t*>(&g_lo[gi]) = lo;
        }
    }
}

// ============================================================================
// Kernel 2: causal flash attention.  grid=1024, 256 thr, 192 KB smem.
// ============================================================================
#define AQ_HI 0
#define AQ_LO 32768
#define AK_HI 65536
#define AK_LO 98304
#define AV_HI 131072
#define AV_LO 163840
#define ASMEM 196608

__global__ void __launch_bounds__(256, 1)
attn_kernel(float* __restrict__ out)
{
    extern __shared__ char sm[];
    const uint32_t smb = smem_u32(sm);
    const int tid = threadIdx.x, lane = tid & 31, w = tid >> 5;
    const int g = lane >> 2, t2 = (lane & 3) << 1;
    const size_t base = (size_t)blockIdx.x * TSEQ * NDIM;

    // stage Q/K/V hi/lo -> swizzled smem (coalesced 128B row-sections)
    for (int sec = 0; sec < 3; ++sec) {
#pragma unroll
        for (int i = 0; i < 8; ++i) {
            int idx = tid + (i << 8);
            int row = idx >> 3, a = idx & 7;
            size_t gi = base + (size_t)row * NDIM + sec * 64 + (a << 3);
            uint4 h = *reinterpret_cast<const uint4*>(&g_hi[gi]);
            uint4 l = *reinterpret_cast<const uint4*>(&g_lo[gi]);
            int off = swz128(row, a << 4);
            *reinterpret_cast<uint4*>(sm + sec * 65536 + off) = h;
            *reinterpret_cast<uint4*>(sm + sec * 65536 + 32768 + off) = l;
        }
    }
    __syncthreads();

    float O[2][8][4];
#pragma unroll
    for (int mt = 0; mt < 2; ++mt)
#pragma unroll
        for (int nt = 0; nt < 8; ++nt)
#pragma unroll
            for (int i = 0; i < 4; ++i) O[mt][nt][i] = 0.f;
    float mrow[2][2] = {{-1e30f, -1e30f}, {-1e30f, -1e30f}};
    float lrow[2][2] = {{0.f, 0.f}, {0.f, 0.f}};

    const int jmax = w >> 1;
    for (int jt = 0; jt <= jmax; ++jt) {
        float S[2][8][4];
#pragma unroll
        for (int mt = 0; mt < 2; ++mt)
#pragma unroll
            for (int nt = 0; nt < 8; ++nt)
#pragma unroll
                for (int i = 0; i < 4; ++i) S[mt][nt][i] = 0.f;

        // ---- S = Q K^T (hi*hi + lo*hi + hi*lo) -----------------------------
        for (int ks = 0; ks < 4; ++ks) {
            uint32_t qh[2][4], ql[2][4];
            int arow  = (w << 5) + (lane & 15);
            int abyte = ((ks << 1) + (lane >> 4)) << 4;
            ldsm4(qh[0], smb + AQ_HI + swz128(arow,      abyte));
            ldsm4(qh[1], smb + AQ_HI + swz128(arow + 16, abyte));
            ldsm4(ql[0], smb + AQ_LO + swz128(arow,      abyte));
            ldsm4(ql[1], smb + AQ_LO + swz128(arow + 16, abyte));
            int kr    = (jt << 6) + (lane & 7);
            int kbyte = ((ks << 1) + ((lane >> 3) & 1)) << 4;
#pragma unroll
            for (int nt = 0; nt < 8; ++nt) {
                uint32_t b0, b1;
                ldsm2(b0, b1, smb + AK_HI + swz128(kr + (nt << 3), kbyte));
                mma16816(S[0][nt], qh[0], b0, b1);
                mma16816(S[1][nt], qh[1], b0, b1);
                mma16816(S[0][nt], ql[0], b0, b1);
                mma16816(S[1][nt], ql[1], b0, b1);
                ldsm2(b0, b1, smb + AK_LO + swz128(kr + (nt << 3), kbyte));
                mma16816(S[0][nt], qh[0], b0, b1);
                mma16816(S[1][nt], qh[1], b0, b1);
            }
        }
        // ---- causal mask on diagonal tile ----------------------------------
        if (jt == jmax) {
#pragma unroll
            for (int mt = 0; mt < 2; ++mt)
#pragma unroll
                for (int nt = 0; nt < 8; ++nt)
#pragma unroll
                    for (int r = 0; r < 2; ++r)
#pragma unroll
                        for (int cc = 0; cc < 2; ++cc) {
                            int col = (jt << 6) + (nt << 3) + t2 + cc;
                            int row = (w << 5) + (mt << 4) + g + (r << 3);
                            if (col > row) S[mt][nt][2 * r + cc] = -1e30f;
                        }
        }
        // ---- online softmax -------------------------------------------------
#pragma unroll
        for (int mt = 0; mt < 2; ++mt)
#pragma unroll
            for (int r = 0; r < 2; ++r) {
                float vmax = -1e30f;
#pragma unroll
                for (int nt = 0; nt < 8; ++nt)
                    vmax = fmaxf(vmax, fmaxf(S[mt][nt][2 * r], S[mt][nt][2 * r + 1]));
                vmax = fmaxf(vmax, __shfl_xor_sync(0xffffffffu, vmax, 1));
                vmax = fmaxf(vmax, __shfl_xor_sync(0xffffffffu, vmax, 2));
                float mnew  = fmaxf(mrow[mt][r], vmax);
                float alpha = ex2(mrow[mt][r] - mnew);
                mrow[mt][r] = mnew;
                float ls = 0.f;
#pragma unroll
                for (int nt = 0; nt < 8; ++nt) {
                    float p0 = ex2(S[mt][nt][2 * r]     - mnew);
                    float p1 = ex2(S[mt][nt][2 * r + 1] - mnew);
                    S[mt][nt][2 * r] = p0; S[mt][nt][2 * r + 1] = p1;
                    ls += p0 + p1;
                }
                lrow[mt][r] = lrow[mt][r] * alpha + ls;
#pragma unroll
                for (int nt = 0; nt < 8; ++nt) {
                    O[mt][nt][2 * r]     *= alpha;
                    O[mt][nt][2 * r + 1] *= alpha;
                }
            }
        // ---- O += P V (P hi/lo, V hi/lo; lo*lo dropped) --------------------
#pragma unroll
        for (int ks = 0; ks < 4; ++ks) {            // MUST unroll: S indexed by ks
            uint32_t ph[2][4], pl[2][4];
#pragma unroll
            for (int mt = 0; mt < 2; ++mt) {
                ph[mt][0] = pk(S[mt][2 * ks][0],     S[mt][2 * ks][1]);
                ph[mt][1] = pk(S[mt][2 * ks][2],     S[mt][2 * ks][3]);
                ph[mt][2] = pk(S[mt][2 * ks + 1][0], S[mt][2 * ks + 1][1]);
                ph[mt][3] = pk(S[mt][2 * ks + 1][2], S[mt][2 * ks + 1][3]);
#pragma unroll
                for (int i = 0; i < 4; ++i) {
                    int tnt = 2 * ks + (i >> 1), tr = i & 1;
                    float2 u = upk(ph[mt][i]);
                    pl[mt][i] = pk(S[mt][tnt][2 * tr] - u.x, S[mt][tnt][2 * tr + 1] - u.y);
                }
            }
            int vr = (jt << 6) + (ks << 4) + (lane & 15);
#pragma unroll
            for (int nt = 0; nt < 8; ++nt) {
                uint32_t b0, b1;
                ldsm2t(b0, b1, smb + AV_HI + swz128(vr, nt << 4));
                mma16816(O[0][nt], ph[0], b0, b1);
                mma16816(O[1][nt], ph[1], b0, b1);
                mma16816(O[0][nt], pl[0], b0, b1);
                mma16816(O[1][nt], pl[1], b0, b1);
                ldsm2t(b0, b1, smb + AV_LO + swz128(vr, nt << 4));
                mma16816(O[0][nt], ph[0], b0, b1);
                mma16816(O[1][nt], ph[1], b0, b1);
            }
        }
    }

    // finalize + store
#pragma unroll
    for (int mt = 0; mt < 2; ++mt)
#pragma unroll
        for (int r = 0; r < 2; ++r) {
            float lt = lrow[mt][r];
            lt += __shfl_xor_sync(0xffffffffu, lt, 1);
            lt += __shfl_xor_sync(0xffffffffu, lt, 2);
            float inv = __frcp_rn(lt);
            int row = (w << 5) + (mt << 4) + g + (r << 3);
            float* op = out + ((size_t)blockIdx.x * TSEQ + row) * HDIM;
#pragma unroll
            for (int nt = 0; nt < 8; ++nt) {
                float2 v = make_float2(O[mt][nt][2 * r] * inv, O[mt][nt][2 * r + 1] * inv);
                *reinterpret_cast<float2*>(op + (nt << 3) + t2) = v;
            }
        }
}

// ---- launch -----------------------------------------------------------------
extern "C" void kernel_launch(void* const* d_in, const int* in_sizes, int n_in,
                              void* d_out, int out_size)
{
    const float* x  = (const float*)d_in[0];
    const float* Wq = (const float*)d_in[1];
    const float* Wk = (const float*)d_in[2];
    const float* Wv = (const float*)d_in[3];
    float* out = (float*)d_out;

    int B = in_sizes[0] / (TSEQ * CDIM);          // 1024
    int Mtiles = (B * TSEQ) / 128;                // 2048

    cudaFuncSetAttribute(proj_kernel, cudaFuncAttributeMaxDynamicSharedMemorySize, PSMEM);
    cudaFuncSetAttribute(attn_kernel, cudaFuncAttributeMaxDynamicSharedMemorySize, ASMEM);

    proj_kernel<<<Mtiles, 256, PSMEM>>>(x, Wq, Wk, Wv);
    attn_kernel<<<B, 256, ASMEM>>>(out);
}

// round 10
// speedup vs baseline: 3.3528x; 1.0777x over previous
#include <cuda_runtime.h>
#include <cuda_bf16.h>
#include <math.h>
#include <stdint.h>

#define BATCH 1024
#define TSEQ  256
#define CDIM  384
#define HDIM  64
#define NDIM  192
#define KC    64

// ---- global scratch: QKV as bf16 hi/lo --------------------------------------
__device__ __align__(16) __nv_bfloat16 g_hi[(size_t)BATCH * TSEQ * NDIM];
__device__ __align__(16) __nv_bfloat16 g_lo[(size_t)BATCH * TSEQ * NDIM];

// ---- helpers ----------------------------------------------------------------
__device__ __forceinline__ uint32_t smem_u32(const void* p) {
    uint32_t a;
    asm("{ .reg .u64 t; cvta.to.shared.u64 t, %1; cvt.u32.u64 %0, t; }" : "=r"(a) : "l"(p));
    return a;
}
// 128B-row tile swizzle (8 16B atoms per row)
__device__ __forceinline__ int swz128(int row, int byteoff) {
    return row * 128 + ((((byteoff >> 4) ^ row) & 7) << 4) + (byteoff & 15);
}
// W tile: 384B rows (24 atoms), swizzle within 8-atom groups
__device__ __forceinline__ int swzW(int k, int byteoff) {
    int atom = byteoff >> 4;
    return k * 384 + (((atom & ~7) | ((atom ^ k) & 7)) << 4) + (byteoff & 15);
}
__device__ __forceinline__ uint32_t pk(float lo, float hi) {   // bf16x2 {hi|lo}
    uint32_t r; asm("cvt.rn.bf16x2.f32 %0, %1, %2;" : "=r"(r) : "f"(hi), "f"(lo)); return r;
}
__device__ __forceinline__ float2 upk(uint32_t v) {            // exact bf16->f32
    float2 f;
    f.x = __uint_as_float(v << 16);
    f.y = __uint_as_float(v & 0xFFFF0000u);
    return f;
}
__device__ __forceinline__ float ex2(float x) {
    float y; asm("ex2.approx.ftz.f32 %0, %1;" : "=f"(y) : "f"(x)); return y;
}
__device__ __forceinline__ void ldsm4(uint32_t* r, uint32_t a) {
    asm volatile("ldmatrix.sync.aligned.m8n8.x4.shared.b16 {%0,%1,%2,%3}, [%4];"
                 : "=r"(r[0]), "=r"(r[1]), "=r"(r[2]), "=r"(r[3]) : "r"(a));
}
__device__ __forceinline__ void ldsm4t(uint32_t* r, uint32_t a) {
    asm volatile("ldmatrix.sync.aligned.m8n8.x4.trans.shared.b16 {%0,%1,%2,%3}, [%4];"
                 : "=r"(r[0]), "=r"(r[1]), "=r"(r[2]), "=r"(r[3]) : "r"(a));
}
__device__ __forceinline__ void ldsm2(uint32_t& r0, uint32_t& r1, uint32_t a) {
    asm volatile("ldmatrix.sync.aligned.m8n8.x2.shared.b16 {%0,%1}, [%2];"
                 : "=r"(r0), "=r"(r1) : "r"(a));
}
__device__ __forceinline__ void ldsm2t(uint32_t& r0, uint32_t& r1, uint32_t a) {
    asm volatile("ldmatrix.sync.aligned.m8n8.x2.trans.shared.b16 {%0,%1}, [%2];"
                 : "=r"(r0), "=r"(r1) : "r"(a));
}
__device__ __forceinline__ void mma16816(float* c, const uint32_t* a,
                                         uint32_t b0, uint32_t b1) {
    asm volatile("mma.sync.aligned.m16n8k16.row.col.f32.bf16.bf16.f32 "
                 "{%0,%1,%2,%3}, {%4,%5,%6,%7}, {%8,%9}, {%0,%1,%2,%3};"
                 : "+f"(c[0]), "+f"(c[1]), "+f"(c[2]), "+f"(c[3])
                 : "r"(a[0]), "r"(a[1]), "r"(a[2]), "r"(a[3]), "r"(b0), "r"(b1));
}

// ============================================================================
// Kernel 1: QKV projection v2.  grid=2048 (M-tiles of 128), 256 thr.
// Warps: 4 m-groups x 2 n-groups. Warp tile M=32, N=96 (12 n-tiles).
// Double-buffered smem, X register-prefetch, ldsm4t for W.
// ============================================================================
#define PSX(buf, part) ((buf) * 32768 + (part) * 16384)            // X hi/lo
#define PSW(buf, part) (65536 + (buf) * 49152 + (part) * 24576)    // W hi/lo
#define PSMEM 163840

__global__ void __launch_bounds__(256, 1)
proj_kernel(const float* __restrict__ x, const float* __restrict__ Wq,
            const float* __restrict__ Wk, const float* __restrict__ Wv)
{
    extern __shared__ char sm[];
    const uint32_t smb = smem_u32(sm);
    const int tid = threadIdx.x, lane = tid & 31, w = tid >> 5;
    const int wm = w & 3, wn = w >> 2;
    const int g = lane >> 2, t2 = (lane & 3) << 1;
    const float* gx = x + (size_t)blockIdx.x * 128 * CDIM;

    float acc[2][12][4];
#pragma unroll
    for (int mt = 0; mt < 2; ++mt)
#pragma unroll
        for (int nt = 0; nt < 12; ++nt)
#pragma unroll
            for (int i = 0; i < 4; ++i) acc[mt][nt][i] = 0.f;

    // prefetch X chunk 0 into registers
    float4 xp[8];
#pragma unroll
    for (int i = 0; i < 8; ++i) {
        int idx = tid + (i << 8);
        xp[i] = *reinterpret_cast<const float4*>(gx + (idx >> 4) * CDIM + ((idx & 15) << 2));
    }

    for (int ch = 0; ch < 6; ++ch) {
        const int kc = ch * KC;
        const int buf = ch & 1;
        // ---- convert + store prefetched X chunk -----------------------------
#pragma unroll
        for (int i = 0; i < 8; ++i) {
            int idx = tid + (i << 8);
            int row = idx >> 4, f4 = idx & 15;
            float4 v = xp[i];
            uint32_t h0 = pk(v.x, v.y), h1 = pk(v.z, v.w);
            float2 u0 = upk(h0), u1 = upk(h1);
            uint32_t l0 = pk(v.x - u0.x, v.y - u0.y);
            uint32_t l1 = pk(v.z - u1.x, v.w - u1.y);
            int off = swz128(row, 8 * f4);
            *reinterpret_cast<uint2*>(sm + PSX(buf, 0) + off) = make_uint2(h0, h1);
            *reinterpret_cast<uint2*>(sm + PSX(buf, 1) + off) = make_uint2(l0, l1);
        }
        // ---- stage W chunk (L2-resident after wave 1) -----------------------
#pragma unroll
        for (int i = 0; i < 12; ++i) {
            int idx = tid + (i << 8);
            int k = idx / 48, f4 = idx % 48;
            int n0 = f4 << 2;
            const float* Wp = (n0 < 64) ? Wq : (n0 < 128) ? Wk : Wv;
            float4 v = *reinterpret_cast<const float4*>(Wp + (kc + k) * HDIM + (n0 & 63));
            uint32_t h0 = pk(v.x, v.y), h1 = pk(v.z, v.w);
            float2 u0 = upk(h0), u1 = upk(h1);
            int off = swzW(k, 2 * n0);
            *reinterpret_cast<uint2*>(sm + PSW(buf, 0) + off) = make_uint2(h0, h1);
            *reinterpret_cast<uint2*>(sm + PSW(buf, 1) + off) =
                make_uint2(pk(v.x - u0.x, v.y - u0.y), pk(v.z - u1.x, v.w - u1.y));
        }
        __syncthreads();
        // ---- prefetch next X chunk (DRAM latency hidden behind mma) ---------
        if (ch < 5) {
#pragma unroll
            for (int i = 0; i < 8; ++i) {
                int idx = tid + (i << 8);
                xp[i] = *reinterpret_cast<const float4*>(
                    gx + (idx >> 4) * CDIM + kc + KC + ((idx & 15) << 2));
            }
        }
        // ---- mma: Ahi*Whi + Alo*Whi + Ahi*Wlo -------------------------------
        for (int ks = 0; ks < 4; ++ks) {
            uint32_t ah[2][4], al[2][4];
            int arow  = (wm << 5) + (lane & 15);
            int abyte = ((ks << 1) + (lane >> 4)) << 4;
            ldsm4(ah[0], smb + PSX(buf, 0) + swz128(arow,      abyte));
            ldsm4(ah[1], smb + PSX(buf, 0) + swz128(arow + 16, abyte));
            ldsm4(al[0], smb + PSX(buf, 1) + swz128(arow,      abyte));
            ldsm4(al[1], smb + PSX(buf, 1) + swz128(arow + 16, abyte));
            int krow = (ks << 4) + (lane & 15);
#pragma unroll
            for (int j = 0; j < 6; ++j) {
                const int n0 = 2 * j;                       // local n-tile pair
                const int ntg = wn * 12 + n0;               // global n-tile
                uint32_t bh[4], bl[4];
                int baddr = swzW(krow, (ntg + (lane >> 4)) << 4);
                ldsm4t(bh, smb + PSW(buf, 0) + baddr);
                mma16816(acc[0][n0],     ah[0], bh[0], bh[1]);
                mma16816(acc[1][n0],     ah[1], bh[0], bh[1]);
                mma16816(acc[0][n0],     al[0], bh[0], bh[1]);
                mma16816(acc[1][n0],     al[1], bh[0], bh[1]);
                mma16816(acc[0][n0 + 1], ah[0], bh[2], bh[3]);
                mma16816(acc[1][n0 + 1], ah[1], bh[2], bh[3]);
                mma16816(acc[0][n0 + 1], al[0], bh[2], bh[3]);
                mma16816(acc[1][n0 + 1], al[1], bh[2], bh[3]);
                ldsm4t(bl, smb + PSW(buf, 1) + baddr);
                mma16816(acc[0][n0],     ah[0], bl[0], bl[1]);
                mma16816(acc[1][n0],     ah[1], bl[0], bl[1]);
                mma16816(acc[0][n0 + 1], ah[0], bl[2], bl[3]);
                mma16816(acc[1][n0 + 1], ah[1], bl[2], bl[3]);
            }
        }
    }

    // ---- epilogue: scale Q by eta, re-split hi/lo, store to scratch ---------
    const float eta = 1.44269504088896340736f * rsqrtf((float)CDIM);
    const size_t grow0 = (size_t)blockIdx.x * 128;
#pragma unroll
    for (int mt = 0; mt < 2; ++mt) {
#pragma unroll
        for (int ntl = 0; ntl < 12; ++ntl) {
            const int ntg = wn * 12 + ntl;
#pragma unroll
            for (int r = 0; r < 2; ++r) {
                float p0 = acc[mt][ntl][2 * r], p1 = acc[mt][ntl][2 * r + 1];
                if (ntg < 8) { p0 *= eta; p1 *= eta; }
                uint32_t hi = pk(p0, p1);
                float2 u = upk(hi);
                uint32_t lo = pk(p0 - u.x, p1 - u.y);
                int row = (wm << 5) + (mt << 4) + g + (r << 3);
                size_t gi = (grow0 + row) * NDIM + (ntg << 3) + t2;
                *reinterpret_cast<uint32_t*>(&g_hi[gi]) = hi;
                *reinterpret_cast<uint32_t*>(&g_lo[gi]) = lo;
            }
        }
    }
}

// ============================================================================
// Kernel 2: causal flash attention (UNCHANGED — verified in Round 8).
// ============================================================================
#define AQ_HI 0
#define AQ_LO 32768
#define AK_HI 65536
#define AK_LO 98304
#define AV_HI 131072
#define AV_LO 163840
#define ASMEM 196608

__global__ void __launch_bounds__(256, 1)
attn_kernel(float* __restrict__ out)
{
    extern __shared__ char sm[];
    const uint32_t smb = smem_u32(sm);
    const int tid = threadIdx.x, lane = tid & 31, w = tid >> 5;
    const int g = lane >> 2, t2 = (lane & 3) << 1;
    const size_t base = (size_t)blockIdx.x * TSEQ * NDIM;

    for (int sec = 0; sec < 3; ++sec) {
#pragma unroll
        for (int i = 0; i < 8; ++i) {
            int idx = tid + (i << 8);
            int row = idx >> 3, a = idx & 7;
            size_t gi = base + (size_t)row * NDIM + sec * 64 + (a << 3);
            uint4 h = *reinterpret_cast<const uint4*>(&g_hi[gi]);
            uint4 l = *reinterpret_cast<const uint4*>(&g_lo[gi]);
            int off = swz128(row, a << 4);
            *reinterpret_cast<uint4*>(sm + sec * 65536 + off) = h;
            *reinterpret_cast<uint4*>(sm + sec * 65536 + 32768 + off) = l;
        }
    }
    __syncthreads();

    float O[2][8][4];
#pragma unroll
    for (int mt = 0; mt < 2; ++mt)
#pragma unroll
        for (int nt = 0; nt < 8; ++nt)
#pragma unroll
            for (int i = 0; i < 4; ++i) O[mt][nt][i] = 0.f;
    float mrow[2][2] = {{-1e30f, -1e30f}, {-1e30f, -1e30f}};
    float lrow[2][2] = {{0.f, 0.f}, {0.f, 0.f}};

    const int jmax = w >> 1;
    for (int jt = 0; jt <= jmax; ++jt) {
        float S[2][8][4];
#pragma unroll
        for (int mt = 0; mt < 2; ++mt)
#pragma unroll
            for (int nt = 0; nt < 8; ++nt)
#pragma unroll
                for (int i = 0; i < 4; ++i) S[mt][nt][i] = 0.f;

        for (int ks = 0; ks < 4; ++ks) {
            uint32_t qh[2][4], ql[2][4];
            int arow  = (w << 5) + (lane & 15);
            int abyte = ((ks << 1) + (lane >> 4)) << 4;
            ldsm4(qh[0], smb + AQ_HI + swz128(arow,      abyte));
            ldsm4(qh[1], smb + AQ_HI + swz128(arow + 16, abyte));
            ldsm4(ql[0], smb + AQ_LO + swz128(arow,      abyte));
            ldsm4(ql[1], smb + AQ_LO + swz128(arow + 16, abyte));
            int kr    = (jt << 6) + (lane & 7);
            int kbyte = ((ks << 1) + ((lane >> 3) & 1)) << 4;
#pragma unroll
            for (int nt = 0; nt < 8; ++nt) {
                uint32_t b0, b1;
                ldsm2(b0, b1, smb + AK_HI + swz128(kr + (nt << 3), kbyte));
                mma16816(S[0][nt], qh[0], b0, b1);
                mma16816(S[1][nt], qh[1], b0, b1);
                mma16816(S[0][nt], ql[0], b0, b1);
                mma16816(S[1][nt], ql[1], b0, b1);
                ldsm2(b0, b1, smb + AK_LO + swz128(kr + (nt << 3), kbyte));
                mma16816(S[0][nt], qh[0], b0, b1);
                mma16816(S[1][nt], qh[1], b0, b1);
            }
        }
        if (jt == jmax) {
#pragma unroll
            for (int mt = 0; mt < 2; ++mt)
#pragma unroll
                for (int nt = 0; nt < 8; ++nt)
#pragma unroll
                    for (int r = 0; r < 2; ++r)
#pragma unroll
                        for (int cc = 0; cc < 2; ++cc) {
                            int col = (jt << 6) + (nt << 3) + t2 + cc;
                            int row = (w << 5) + (mt << 4) + g + (r << 3);
                            if (col > row) S[mt][nt][2 * r + cc] = -1e30f;
                        }
        }
#pragma unroll
        for (int mt = 0; mt < 2; ++mt)
#pragma unroll
            for (int r = 0; r < 2; ++r) {
                float vmax = -1e30f;
#pragma unroll
                for (int nt = 0; nt < 8; ++nt)
                    vmax = fmaxf(vmax, fmaxf(S[mt][nt][2 * r], S[mt][nt][2 * r + 1]));
                vmax = fmaxf(vmax, __shfl_xor_sync(0xffffffffu, vmax, 1));
                vmax = fmaxf(vmax, __shfl_xor_sync(0xffffffffu, vmax, 2));
                float mnew  = fmaxf(mrow[mt][r], vmax);
                float alpha = ex2(mrow[mt][r] - mnew);
                mrow[mt][r] = mnew;
                float ls = 0.f;
#pragma unroll
                for (int nt = 0; nt < 8; ++nt) {
                    float p0 = ex2(S[mt][nt][2 * r]     - mnew);
                    float p1 = ex2(S[mt][nt][2 * r + 1] - mnew);
                    S[mt][nt][2 * r] = p0; S[mt][nt][2 * r + 1] = p1;
                    ls += p0 + p1;
                }
                lrow[mt][r] = lrow[mt][r] * alpha + ls;
#pragma unroll
                for (int nt = 0; nt < 8; ++nt) {
                    O[mt][nt][2 * r]     *= alpha;
                    O[mt][nt][2 * r + 1] *= alpha;
                }
            }
#pragma unroll
        for (int ks = 0; ks < 4; ++ks) {
            uint32_t ph[2][4], pl[2][4];
#pragma unroll
            for (int mt = 0; mt < 2; ++mt) {
                ph[mt][0] = pk(S[mt][2 * ks][0],     S[mt][2 * ks][1]);
                ph[mt][1] = pk(S[mt][2 * ks][2],     S[mt][2 * ks][3]);
                ph[mt][2] = pk(S[mt][2 * ks + 1][0], S[mt][2 * ks + 1][1]);
                ph[mt][3] = pk(S[mt][2 * ks + 1][2], S[mt][2 * ks + 1][3]);
#pragma unroll
                for (int i = 0; i < 4; ++i) {
                    int tnt = 2 * ks + (i >> 1), tr = i & 1;
                    float2 u = upk(ph[mt][i]);
                    pl[mt][i] = pk(S[mt][tnt][2 * tr] - u.x, S[mt][tnt][2 * tr + 1] - u.y);
                }
            }
            int vr = (jt << 6) + (ks << 4) + (lane & 15);
#pragma unroll
            for (int nt = 0; nt < 8; ++nt) {
                uint32_t b0, b1;
                ldsm2t(b0, b1, smb + AV_HI + swz128(vr, nt << 4));
                mma16816(O[0][nt], ph[0], b0, b1);
                mma16816(O[1][nt], ph[1], b0, b1);
                mma16816(O[0][nt], pl[0], b0, b1);
                mma16816(O[1][nt], pl[1], b0, b1);
                ldsm2t(b0, b1, smb + AV_LO + swz128(vr, nt << 4));
                mma16816(O[0][nt], ph[0], b0, b1);
                mma16816(O[1][nt], ph[1], b0, b1);
            }
        }
    }

#pragma unroll
    for (int mt = 0; mt < 2; ++mt)
#pragma unroll
        for (int r = 0; r < 2; ++r) {
            float lt = lrow[mt][r];
            lt += __shfl_xor_sync(0xffffffffu, lt, 1);
            lt += __shfl_xor_sync(0xffffffffu, lt, 2);
            float inv = __frcp_rn(lt);
            int row = (w << 5) + (mt << 4) + g + (r << 3);
            float* op = out + ((size_t)blockIdx.x * TSEQ + row) * HDIM;
#pragma unroll
            for (int nt = 0; nt < 8; ++nt) {
                float2 v = make_float2(O[mt][nt][2 * r] * inv, O[mt][nt][2 * r + 1] * inv);
                *reinterpret_cast<float2*>(op + (nt << 3) + t2) = v;
            }
        }
}

// ---- launch -----------------------------------------------------------------
extern "C" void kernel_launch(void* const* d_in, const int* in_sizes, int n_in,
                              void* d_out, int out_size)
{
    const float* x  = (const float*)d_in[0];
    const float* Wq = (const float*)d_in[1];
    const float* Wk = (const float*)d_in[2];
    const float* Wv = (const float*)d_in[3];
    float* out = (float*)d_out;

    int B = in_sizes[0] / (TSEQ * CDIM);          // 1024
    int Mtiles = (B * TSEQ) / 128;                // 2048

    cudaFuncSetAttribute(proj_kernel, cudaFuncAttributeMaxDynamicSharedMemorySize, PSMEM);
    cudaFuncSetAttribute(attn_kernel, cudaFuncAttributeMaxDynamicSharedMemorySize, ASMEM);

    proj_kernel<<<Mtiles, 256, PSMEM>>>(x, Wq, Wk, Wv);
    attn_kernel<<<B, 256, ASMEM>>>(out);
}

// round 11
// speedup vs baseline: 3.3616x; 1.0026x over previous
#include <cuda_runtime.h>
#include <cuda_bf16.h>
#include <math.h>
#include <stdint.h>

#define BATCH 1024
#define TSEQ  256
#define CDIM  384
#define HDIM  64
#define NDIM  192
#define KC    32
#define NCH   12

// ---- global scratch ----------------------------------------------------------
__device__ __align__(16) __nv_bfloat16 g_hi[(size_t)BATCH * TSEQ * NDIM];
__device__ __align__(16) __nv_bfloat16 g_lo[(size_t)BATCH * TSEQ * NDIM];
__device__ __align__(16) __nv_bfloat16 gW_hi[CDIM * NDIM];   // pre-swizzled
__device__ __align__(16) __nv_bfloat16 gW_lo[CDIM * NDIM];

// ---- helpers ----------------------------------------------------------------
__device__ __forceinline__ uint32_t smem_u32(const void* p) {
    uint32_t a;
    asm("{ .reg .u64 t; cvta.to.shared.u64 t, %1; cvt.u32.u64 %0, t; }" : "=r"(a) : "l"(p));
    return a;
}
// 128B-row tile swizzle (8 16B atoms per row)
__device__ __forceinline__ int swz128(int row, int byteoff) {
    return row * 128 + ((((byteoff >> 4) ^ row) & 7) << 4) + (byteoff & 15);
}
// W tile: 384B rows (24 atoms), swizzle within 8-atom groups (uses k&7 only)
__device__ __forceinline__ int swzW(int k, int byteoff) {
    int atom = byteoff >> 4;
    return k * 384 + (((atom & ~7) | ((atom ^ k) & 7)) << 4) + (byteoff & 15);
}
__device__ __forceinline__ uint32_t pk(float lo, float hi) {   // bf16x2 {hi|lo}
    uint32_t r; asm("cvt.rn.bf16x2.f32 %0, %1, %2;" : "=r"(r) : "f"(hi), "f"(lo)); return r;
}
__device__ __forceinline__ float2 upk(uint32_t v) {            // exact bf16->f32
    float2 f;
    f.x = __uint_as_float(v << 16);
    f.y = __uint_as_float(v & 0xFFFF0000u);
    return f;
}
__device__ __forceinline__ float ex2(float x) {
    float y; asm("ex2.approx.ftz.f32 %0, %1;" : "=f"(y) : "f"(x)); return y;
}
__device__ __forceinline__ void ldsm4(uint32_t* r, uint32_t a) {
    asm volatile("ldmatrix.sync.aligned.m8n8.x4.shared.b16 {%0,%1,%2,%3}, [%4];"
                 : "=r"(r[0]), "=r"(r[1]), "=r"(r[2]), "=r"(r[3]) : "r"(a));
}
__device__ __forceinline__ void ldsm4t(uint32_t* r, uint32_t a) {
    asm volatile("ldmatrix.sync.aligned.m8n8.x4.trans.shared.b16 {%0,%1,%2,%3}, [%4];"
                 : "=r"(r[0]), "=r"(r[1]), "=r"(r[2]), "=r"(r[3]) : "r"(a));
}
__device__ __forceinline__ void ldsm2(uint32_t& r0, uint32_t& r1, uint32_t a) {
    asm volatile("ldmatrix.sync.aligned.m8n8.x2.shared.b16 {%0,%1}, [%2];"
                 : "=r"(r0), "=r"(r1) : "r"(a));
}
__device__ __forceinline__ void ldsm2t(uint32_t& r0, uint32_t& r1, uint32_t a) {
    asm volatile("ldmatrix.sync.aligned.m8n8.x2.trans.shared.b16 {%0,%1}, [%2];"
                 : "=r"(r0), "=r"(r1) : "r"(a));
}
__device__ __forceinline__ void mma16816(float* c, const uint32_t* a,
                                         uint32_t b0, uint32_t b1) {
    asm volatile("mma.sync.aligned.m16n8k16.row.col.f32.bf16.bf16.f32 "
                 "{%0,%1,%2,%3}, {%4,%5,%6,%7}, {%8,%9}, {%0,%1,%2,%3};"
                 : "+f"(c[0]), "+f"(c[1]), "+f"(c[2]), "+f"(c[3])
                 : "r"(a[0]), "r"(a[1]), "r"(a[2]), "r"(a[3]), "r"(b0), "r"(b1));
}

// ============================================================================
// Kernel 0: pre-convert W -> bf16 hi/lo, pre-swizzled [384k x 192n] layout.
// ============================================================================
__global__ void prep_w(const float* __restrict__ Wq, const float* __restrict__ Wk,
                       const float* __restrict__ Wv) {
    int idx = blockIdx.x * 256 + threadIdx.x;      // over 384*192
    if (idx >= CDIM * NDIM) return;
    int k = idx / NDIM, n = idx % NDIM;
    const float* Wp = (n < 64) ? Wq : (n < 128) ? Wk : Wv;
    float v = Wp[k * HDIM + (n & 63)];
    uint32_t h = pk(v, v);                          // lane .x = bf16(v)
    float2 u = upk(h);
    int off = swzW(k, 2 * n);
    *reinterpret_cast<__nv_bfloat16*>(reinterpret_cast<char*>(gW_hi) + off) =
        __ushort_as_bfloat16((unsigned short)(h & 0xFFFFu));
    uint32_t l = pk(v - u.x, 0.f);
    *reinterpret_cast<__nv_bfloat16*>(reinterpret_cast<char*>(gW_lo) + off) =
        __ushort_as_bfloat16((unsigned short)(l & 0xFFFFu));
}

// ============================================================================
// Kernel 1: QKV projection v3.  grid=4096 (M-tiles of 64), 256 thr, 2 CTA/SM.
// Warp tile M=16, N=96.  X: hi|lo packed per 128B row.  W: preconverted bf16.
// ============================================================================
#define PSX(buf)       ((buf) * 8192)                           // X: 64 rows x 128B
#define PSW(buf, part) (16384 + (buf) * 24576 + (part) * 12288) // W: 32k x 384B
#define PSMEM 65536

__global__ void __launch_bounds__(256, 2)
proj_kernel(const float* __restrict__ x)
{
    extern __shared__ char sm[];
    const uint32_t smb = smem_u32(sm);
    const int tid = threadIdx.x, lane = tid & 31, w = tid >> 5;
    const int wm = w & 3, wn = w >> 2;
    const int g = lane >> 2, t2 = (lane & 3) << 1;
    const float* gx = x + (size_t)blockIdx.x * 64 * CDIM;
    const char* gwh = reinterpret_cast<const char*>(gW_hi);
    const char* gwl = reinterpret_cast<const char*>(gW_lo);

    float acc[12][4];
#pragma unroll
    for (int nt = 0; nt < 12; ++nt)
#pragma unroll
        for (int i = 0; i < 4; ++i) acc[nt][i] = 0.f;

    // prefetch chunk 0: X (2 float4/thread) + W (3+3 uint4/thread)
    float4 xp[2];
    uint4  wh[3], wl[3];
#pragma unroll
    for (int i = 0; i < 2; ++i) {
        int idx = tid + (i << 8);
        xp[i] = *reinterpret_cast<const float4*>(gx + (idx >> 3) * CDIM + ((idx & 7) << 2));
    }
#pragma unroll
    for (int i = 0; i < 3; ++i) {
        int boff = (tid + (i << 8)) << 4;
        wh[i] = *reinterpret_cast<const uint4*>(gwh + boff);
        wl[i] = *reinterpret_cast<const uint4*>(gwl + boff);
    }

    for (int ch = 0; ch < NCH; ++ch) {
        const int buf = ch & 1;
        // ---- store prefetched X (convert) + W (raw copy) --------------------
#pragma unroll
        for (int i = 0; i < 2; ++i) {
            int idx = tid + (i << 8);
            int row = idx >> 3, f4 = idx & 7;
            float4 v = xp[i];
            uint32_t h0 = pk(v.x, v.y), h1 = pk(v.z, v.w);
            float2 u0 = upk(h0), u1 = upk(h1);
            uint32_t l0 = pk(v.x - u0.x, v.y - u0.y);
            uint32_t l1 = pk(v.z - u1.x, v.w - u1.y);
            *reinterpret_cast<uint2*>(sm + PSX(buf) + swz128(row, f4 << 3)) =
                make_uint2(h0, h1);
            *reinterpret_cast<uint2*>(sm + PSX(buf) + swz128(row, 64 + (f4 << 3))) =
                make_uint2(l0, l1);
        }
#pragma unroll
        for (int i = 0; i < 3; ++i) {
            int boff = (tid + (i << 8)) << 4;
            *reinterpret_cast<uint4*>(sm + PSW(buf, 0) + boff) = wh[i];
            *reinterpret_cast<uint4*>(sm + PSW(buf, 1) + boff) = wl[i];
        }
        __syncthreads();
        // ---- prefetch next chunk --------------------------------------------
        if (ch < NCH - 1) {
            const int kc = (ch + 1) * KC;
#pragma unroll
            for (int i = 0; i < 2; ++i) {
                int idx = tid + (i << 8);
                xp[i] = *reinterpret_cast<const float4*>(
                    gx + (idx >> 3) * CDIM + kc + ((idx & 7) << 2));
            }
            const int wslab = (ch + 1) * 12288;
#pragma unroll
            for (int i = 0; i < 3; ++i) {
                int boff = wslab + ((tid + (i << 8)) << 4);
                wh[i] = *reinterpret_cast<const uint4*>(gwh + boff);
                wl[i] = *reinterpret_cast<const uint4*>(gwl + boff);
            }
        }
        // ---- mma: Ahi*Whi + Alo*Whi + Ahi*Wlo -------------------------------
#pragma unroll
        for (int ks = 0; ks < 2; ++ks) {
            uint32_t ah[4], al[4];
            int arow  = (wm << 4) + (lane & 15);
            int abyte = (ks << 5) + ((lane >> 4) << 4);
            ldsm4(ah, smb + PSX(buf) + swz128(arow, abyte));
            ldsm4(al, smb + PSX(buf) + swz128(arow, 64 + abyte));
            int krow = (ks << 4) + (lane & 15);
#pragma unroll
            for (int j = 0; j < 6; ++j) {
                const int n0 = 2 * j;
                const int ntg = wn * 12 + n0;
                uint32_t bh[4], bl[4];
                int baddr = swzW(krow, (ntg + (lane >> 4)) << 4);
                ldsm4t(bh, smb + PSW(buf, 0) + baddr);
                mma16816(acc[n0],     ah, bh[0], bh[1]);
                mma16816(acc[n0],     al, bh[0], bh[1]);
                mma16816(acc[n0 + 1], ah, bh[2], bh[3]);
                mma16816(acc[n0 + 1], al, bh[2], bh[3]);
                ldsm4t(bl, smb + PSW(buf, 1) + baddr);
                mma16816(acc[n0],     ah, bl[0], bl[1]);
                mma16816(acc[n0 + 1], ah, bl[2], bl[3]);
            }
        }
    }

    // ---- epilogue: scale Q by eta, re-split hi/lo, store to scratch ---------
    const float eta = 1.44269504088896340736f * rsqrtf((float)CDIM);
    const size_t grow0 = (size_t)blockIdx.x * 64;
#pragma unroll
    for (int ntl = 0; ntl < 12; ++ntl) {
        const int ntg = wn * 12 + ntl;
#pragma unroll
        for (int r = 0; r < 2; ++r) {
            float p0 = acc[ntl][2 * r], p1 = acc[ntl][2 * r + 1];
            if (ntg < 8) { p0 *= eta; p1 *= eta; }
            uint32_t hi = pk(p0, p1);
            float2 u = upk(hi);
            uint32_t lo = pk(p0 - u.x, p1 - u.y);
            int row = (wm << 4) + g + (r << 3);
            size_t gi = (grow0 + row) * NDIM + (ntg << 3) + t2;
            *reinterpret_cast<uint32_t*>(&g_hi[gi]) = hi;
            *reinterpret_cast<uint32_t*>(&g_lo[gi]) = lo;
        }
    }
}

// ============================================================================
// Kernel 2: causal flash attention, balanced: warp w owns 16-row blocks
// {w, 15-w} -> every warp does exactly 5 (block x 64-col-tile) work units.
// ============================================================================
#define AQ_HI 0
#define AQ_LO 32768
#define AK_HI 65536
#define AK_LO 98304
#define AV_HI 131072
#define AV_LO 163840
#define ASMEM 196608

__global__ void __launch_bounds__(256, 1)
attn_kernel(float* __restrict__ out)
{
    extern __shared__ char sm[];
    const uint32_t smb = smem_u32(sm);
    const int tid = threadIdx.x, lane = tid & 31, w = tid >> 5;
    const int g = lane >> 2, t2 = (lane & 3) << 1;
    const size_t base = (size_t)blockIdx.x * TSEQ * NDIM;

    // block row bases and diagonal tile indices for this warp's two blocks
    const int rbase0 = w << 4,        rbase1 = (15 - w) << 4;
    const int jmax0  = w >> 2,        jmax1  = (15 - w) >> 2;   // jmax1 >= jmax0

    for (int sec = 0; sec < 3; ++sec) {
#pragma unroll
        for (int i = 0; i < 8; ++i) {
            int idx = tid + (i << 8);
            int row = idx >> 3, a = idx & 7;
            size_t gi = base + (size_t)row * NDIM + sec * 64 + (a << 3);
            uint4 h = *reinterpret_cast<const uint4*>(&g_hi[gi]);
            uint4 l = *reinterpret_cast<const uint4*>(&g_lo[gi]);
            int off = swz128(row, a << 4);
            *reinterpret_cast<uint4*>(sm + sec * 65536 + off) = h;
            *reinterpret_cast<uint4*>(sm + sec * 65536 + 32768 + off) = l;
        }
    }
    __syncthreads();

    float O[2][8][4];
#pragma unroll
    for (int mt = 0; mt < 2; ++mt)
#pragma unroll
        for (int nt = 0; nt < 8; ++nt)
#pragma unroll
            for (int i = 0; i < 4; ++i) O[mt][nt][i] = 0.f;
    float mrow[2][2] = {{-1e30f, -1e30f}, {-1e30f, -1e30f}};
    float lrow[2][2] = {{0.f, 0.f}, {0.f, 0.f}};

    for (int jt = 0; jt <= jmax1; ++jt) {
        const bool act0 = (jt <= jmax0);            // block 1 always active
        float S[2][8][4];
#pragma unroll
        for (int mt = 0; mt < 2; ++mt)
#pragma unroll
            for (int nt = 0; nt < 8; ++nt)
#pragma unroll
                for (int i = 0; i < 4; ++i) S[mt][nt][i] = 0.f;

        // ---- S = Q K^T -------------------------------------------------------
        for (int ks = 0; ks < 4; ++ks) {
            uint32_t qh[2][4], ql[2][4];
            int abyte = ((ks << 1) + (lane >> 4)) << 4;
            int lrow16 = lane & 15;
            if (act0) {
                ldsm4(qh[0], smb + AQ_HI + swz128(rbase0 + lrow16, abyte));
                ldsm4(ql[0], smb + AQ_LO + swz128(rbase0 + lrow16, abyte));
            }
            ldsm4(qh[1], smb + AQ_HI + swz128(rbase1 + lrow16, abyte));
            ldsm4(ql[1], smb + AQ_LO + swz128(rbase1 + lrow16, abyte));
            int kr    = (jt << 6) + (lane & 7);
            int kbyte = ((ks << 1) + ((lane >> 3) & 1)) << 4;
#pragma unroll
            for (int nt = 0; nt < 8; ++nt) {
                uint32_t b0, b1;
                ldsm2(b0, b1, smb + AK_HI + swz128(kr + (nt << 3), kbyte));
                if (act0) {
                    mma16816(S[0][nt], qh[0], b0, b1);
                    mma16816(S[0][nt], ql[0], b0, b1);
                }
                mma16816(S[1][nt], qh[1], b0, b1);
                mma16816(S[1][nt], ql[1], b0, b1);
                ldsm2(b0, b1, smb + AK_LO + swz128(kr + (nt << 3), kbyte));
                if (act0) mma16816(S[0][nt], qh[0], b0, b1);
                mma16816(S[1][nt], qh[1], b0, b1);
            }
        }
        // ---- causal mask on each block's diagonal tile -----------------------
#pragma unroll
        for (int mt = 0; mt < 2; ++mt) {
            const int jm = (mt == 0) ? jmax0 : jmax1;
            const int rb = (mt == 0) ? rbase0 : rbase1;
            if (jt == jm) {
#pragma unroll
                for (int nt = 0; nt < 8; ++nt)
#pragma unroll
                    for (int r = 0; r < 2; ++r)
#pragma unroll
                        for (int cc = 0; cc < 2; ++cc) {
                            int col = (jt << 6) + (nt << 3) + t2 + cc;
                            int row = rb + g + (r << 3);
                            if (col > row) S[mt][nt][2 * r + cc] = -1e30f;
                        }
            }
        }
        // ---- online softmax (active blocks only) -----------------------------
#pragma unroll
        for (int mt = 0; mt < 2; ++mt) {
            if (mt == 0 && !act0) continue;
#pragma unroll
            for (int r = 0; r < 2; ++r) {
                float vmax = -1e30f;
#pragma unroll
                for (int nt = 0; nt < 8; ++nt)
                    vmax = fmaxf(vmax, fmaxf(S[mt][nt][2 * r], S[mt][nt][2 * r + 1]));
                vmax = fmaxf(vmax, __shfl_xor_sync(0xffffffffu, vmax, 1));
                vmax = fmaxf(vmax, __shfl_xor_sync(0xffffffffu, vmax, 2));
                float mnew  = fmaxf(mrow[mt][r], vmax);
                float alpha = ex2(mrow[mt][r] - mnew);
                mrow[mt][r] = mnew;
                float ls = 0.f;
#pragma unroll
                for (int nt = 0; nt < 8; ++nt) {
                    float p0 = ex2(S[mt][nt][2 * r]     - mnew);
                    float p1 = ex2(S[mt][nt][2 * r + 1] - mnew);
                    S[mt][nt][2 * r] = p0; S[mt][nt][2 * r + 1] = p1;
                    ls += p0 + p1;
                }
                lrow[mt][r] = lrow[mt][r] * alpha + ls;
#pragma unroll
                for (int nt = 0; nt < 8; ++nt) {
                    O[mt][nt][2 * r]     *= alpha;
                    O[mt][nt][2 * r + 1] *= alpha;
                }
            }
        }
        // ---- O += P V (active blocks only) -----------------------------------
#pragma unroll
        for (int ks = 0; ks < 4; ++ks) {
            uint32_t ph[2][4], pl[2][4];
#pragma unroll
            for (int mt = 0; mt < 2; ++mt) {
                if (mt == 0 && !act0) continue;
                ph[mt][0] = pk(S[mt][2 * ks][0],     S[mt][2 * ks][1]);
                ph[mt][1] = pk(S[mt][2 * ks][2],     S[mt][2 * ks][3]);
                ph[mt][2] = pk(S[mt][2 * ks + 1][0], S[mt][2 * ks + 1][1]);
                ph[mt][3] = pk(S[mt][2 * ks + 1][2], S[mt][2 * ks + 1][3]);
#pragma unroll
                for (int i = 0; i < 4; ++i) {
                    int tnt = 2 * ks + (i >> 1), tr = i & 1;
                    float2 u = upk(ph[mt][i]);
                    pl[mt][i] = pk(S[mt][tnt][2 * tr] - u.x, S[mt][tnt][2 * tr + 1] - u.y);
                }
            }
            int vr = (jt << 6) + (ks << 4) + (lane & 15);
#pragma unroll
            for (int nt = 0; nt < 8; ++nt) {
                uint32_t b0, b1;
                ldsm2t(b0, b1, smb + AV_HI + swz128(vr, nt << 4));
                if (act0) {
                    mma16816(O[0][nt], ph[0], b0, b1);
                    mma16816(O[0][nt], pl[0], b0, b1);
                }
                mma16816(O[1][nt], ph[1], b0, b1);
                mma16816(O[1][nt], pl[1], b0, b1);
                ldsm2t(b0, b1, smb + AV_LO + swz128(vr, nt << 4));
                if (act0) mma16816(O[0][nt], ph[0], b0, b1);
                mma16816(O[1][nt], ph[1], b0, b1);
            }
        }
    }

    // ---- finalize + store ----------------------------------------------------
#pragma unroll
    for (int mt = 0; mt < 2; ++mt) {
        const int rb = (mt == 0) ? rbase0 : rbase1;
#pragma unroll
        for (int r = 0; r < 2; ++r) {
            float lt = lrow[mt][r];
            lt += __shfl_xor_sync(0xffffffffu, lt, 1);
            lt += __shfl_xor_sync(0xffffffffu, lt, 2);
            float inv = __frcp_rn(lt);
            int row = rb + g + (r << 3);
            float* op = out + ((size_t)blockIdx.x * TSEQ + row) * HDIM;
#pragma unroll
            for (int nt = 0; nt < 8; ++nt) {
                float2 v = make_float2(O[mt][nt][2 * r] * inv, O[mt][nt][2 * r + 1] * inv);
                *reinterpret_cast<float2*>(op + (nt << 3) + t2) = v;
            }
        }
    }
}

// ---- launch -----------------------------------------------------------------
extern "C" void kernel_launch(void* const* d_in, const int* in_sizes, int n_in,
                              void* d_out, int out_size)
{
    const float* x  = (const float*)d_in[0];
    const float* Wq = (const float*)d_in[1];
    const float* Wk = (const float*)d_in[2];
    const float* Wv = (const float*)d_in[3];
    float* out = (float*)d_out;

    int B = in_sizes[0] / (TSEQ * CDIM);          // 1024
    int Mtiles = (B * TSEQ) / 64;                 // 4096

    cudaFuncSetAttribute(proj_kernel, cudaFuncAttributeMaxDynamicSharedMemorySize, PSMEM);
    cudaFuncSetAttribute(attn_kernel, cudaFuncAttributeMaxDynamicSharedMemorySize, ASMEM);

    prep_w<<<(CDIM * NDIM + 255) / 256, 256>>>(Wq, Wk, Wv);
    proj_kernel<<<Mtiles, 256, PSMEM>>>(x);
    attn_kernel<<<B, 256, ASMEM>>>(out);
}

// round 12
// speedup vs baseline: 7.5820x; 2.2555x over previous
#include <cuda_runtime.h>
#include <cuda_fp16.h>
#include <math.h>
#include <stdint.h>

#define BATCH 1024
#define TSEQ  256
#define CDIM  384
#define HDIM  64
#define NDIM  192
#define KC    64

// ---- global scratch ----------------------------------------------------------
__device__ __align__(16) __half g_qkv[(size_t)BATCH * TSEQ * NDIM];  // fp16 QKV
__device__ __align__(16) __half gW[CDIM * NDIM];                     // pre-swizzled fp16 W

// ---- helpers ----------------------------------------------------------------
__device__ __forceinline__ uint32_t smem_u32(const void* p) {
    uint32_t a;
    asm("{ .reg .u64 t; cvta.to.shared.u64 t, %1; cvt.u32.u64 %0, t; }" : "=r"(a) : "l"(p));
    return a;
}
// 128B-row tile swizzle (8 16B atoms per row)
__device__ __forceinline__ int swz128(int row, int byteoff) {
    return row * 128 + ((((byteoff >> 4) ^ row) & 7) << 4) + (byteoff & 15);
}
// W tile: 384B rows (24 atoms), swizzle within 8-atom groups
__device__ __forceinline__ int swzW(int k, int byteoff) {
    int atom = byteoff >> 4;
    return k * 384 + (((atom & ~7) | ((atom ^ k) & 7)) << 4) + (byteoff & 15);
}
__device__ __forceinline__ uint32_t pkh(float lo, float hi) {   // f16x2 {hi|lo}
    uint32_t r; asm("cvt.rn.f16x2.f32 %0, %1, %2;" : "=r"(r) : "f"(hi), "f"(lo)); return r;
}
__device__ __forceinline__ float ex2(float x) {
    float y; asm("ex2.approx.ftz.f32 %0, %1;" : "=f"(y) : "f"(x)); return y;
}
__device__ __forceinline__ void ldsm4(uint32_t* r, uint32_t a) {
    asm volatile("ldmatrix.sync.aligned.m8n8.x4.shared.b16 {%0,%1,%2,%3}, [%4];"
                 : "=r"(r[0]), "=r"(r[1]), "=r"(r[2]), "=r"(r[3]) : "r"(a));
}
__device__ __forceinline__ void ldsm4t(uint32_t* r, uint32_t a) {
    asm volatile("ldmatrix.sync.aligned.m8n8.x4.trans.shared.b16 {%0,%1,%2,%3}, [%4];"
                 : "=r"(r[0]), "=r"(r[1]), "=r"(r[2]), "=r"(r[3]) : "r"(a));
}
__device__ __forceinline__ void ldsm2(uint32_t& r0, uint32_t& r1, uint32_t a) {
    asm volatile("ldmatrix.sync.aligned.m8n8.x2.shared.b16 {%0,%1}, [%2];"
                 : "=r"(r0), "=r"(r1) : "r"(a));
}
__device__ __forceinline__ void ldsm2t(uint32_t& r0, uint32_t& r1, uint32_t a) {
    asm volatile("ldmatrix.sync.aligned.m8n8.x2.trans.shared.b16 {%0,%1}, [%2];"
                 : "=r"(r0), "=r"(r1) : "r"(a));
}
__device__ __forceinline__ void mma16816(float* c, const uint32_t* a,
                                         uint32_t b0, uint32_t b1) {
    asm volatile("mma.sync.aligned.m16n8k16.row.col.f32.f16.f16.f32 "
                 "{%0,%1,%2,%3}, {%4,%5,%6,%7}, {%8,%9}, {%0,%1,%2,%3};"
                 : "+f"(c[0]), "+f"(c[1]), "+f"(c[2]), "+f"(c[3])
                 : "r"(a[0]), "r"(a[1]), "r"(a[2]), "r"(a[3]), "r"(b0), "r"(b1));
}

// ============================================================================
// Kernel 0: pre-convert W -> fp16, pre-swizzled [384k x 192n] layout.
// ============================================================================
__global__ void prep_w(const float* __restrict__ Wq, const float* __restrict__ Wk,
                       const float* __restrict__ Wv) {
    int idx = blockIdx.x * 256 + threadIdx.x;      // over 384*192
    if (idx >= CDIM * NDIM) return;
    int k = idx / NDIM, n = idx % NDIM;
    const float* Wp = (n < 64) ? Wq : (n < 128) ? Wk : Wv;
    float v = Wp[k * HDIM + (n & 63)];
    *reinterpret_cast<__half*>(reinterpret_cast<char*>(gW) + swzW(k, 2 * n)) =
        __float2half_rn(v);
}

// ============================================================================
// Kernel 1: QKV projection (fp16 single-chain).  grid=2048 (M-tiles of 128).
// Warps: 4 m x 2 n; warp tile M=32, N=96.  Double-buffered, X reg-prefetch.
// ============================================================================
#define PSX(buf) ((buf) * 16384)            // X: 128 rows x 128B (64 fp16)
#define PSW(buf) (32768 + (buf) * 24576)    // W: 64k x 384B
#define PSMEM 81920

__global__ void __launch_bounds__(256, 1)
proj_kernel(const float* __restrict__ x)
{
    extern __shared__ char sm[];
    const uint32_t smb = smem_u32(sm);
    const int tid = threadIdx.x, lane = tid & 31, w = tid >> 5;
    const int wm = w & 3, wn = w >> 2;
    const int g = lane >> 2, t2 = (lane & 3) << 1;
    const float* gx = x + (size_t)blockIdx.x * 128 * CDIM;
    const char* gw = reinterpret_cast<const char*>(gW);

    float acc[2][12][4];
#pragma unroll
    for (int mt = 0; mt < 2; ++mt)
#pragma unroll
        for (int nt = 0; nt < 12; ++nt)
#pragma unroll
            for (int i = 0; i < 4; ++i) acc[mt][nt][i] = 0.f;

    // prefetch X chunk 0
    float4 xp[8];
#pragma unroll
    for (int i = 0; i < 8; ++i) {
        int idx = tid + (i << 8);
        xp[i] = *reinterpret_cast<const float4*>(gx + (idx >> 4) * CDIM + ((idx & 15) << 2));
    }

    for (int ch = 0; ch < 6; ++ch) {
        const int buf = ch & 1;
        // ---- store prefetched X chunk (f32 -> fp16, swizzled) ----------------
#pragma unroll
        for (int i = 0; i < 8; ++i) {
            int idx = tid + (i << 8);
            int row = idx >> 4, f4 = idx & 15;
            float4 v = xp[i];
            *reinterpret_cast<uint2*>(sm + PSX(buf) + swz128(row, f4 << 3)) =
                make_uint2(pkh(v.x, v.y), pkh(v.z, v.w));
        }
        // ---- stage W chunk (raw uint4 copy of preconverted fp16) -------------
        {
            const int slab = ch * 24576;
#pragma unroll
            for (int i = 0; i < 6; ++i) {
                int boff = (tid + (i << 8)) << 4;
                *reinterpret_cast<uint4*>(sm + PSW(buf) + boff) =
                    *reinterpret_cast<const uint4*>(gw + slab + boff);
            }
        }
        __syncthreads();
        // ---- prefetch next X chunk -------------------------------------------
        if (ch < 5) {
            const int kc = (ch + 1) * KC;
#pragma unroll
            for (int i = 0; i < 8; ++i) {
                int idx = tid + (i << 8);
                xp[i] = *reinterpret_cast<const float4*>(
                    gx + (idx >> 4) * CDIM + kc + ((idx & 15) << 2));
            }
        }
        // ---- mma: single fp16 chain ------------------------------------------
#pragma unroll
        for (int ks = 0; ks < 4; ++ks) {
            uint32_t ah[2][4];
            int arow  = (wm << 5) + (lane & 15);
            int abyte = ((ks << 1) + (lane >> 4)) << 4;
            ldsm4(ah[0], smb + PSX(buf) + swz128(arow,      abyte));
            ldsm4(ah[1], smb + PSX(buf) + swz128(arow + 16, abyte));
            int krow = (ks << 4) + (lane & 15);
#pragma unroll
            for (int j = 0; j < 6; ++j) {
                const int n0 = 2 * j;
                const int ntg = wn * 12 + n0;
                uint32_t bh[4];
                ldsm4t(bh, smb + PSW(buf) + swzW(krow, (ntg + (lane >> 4)) << 4));
                mma16816(acc[0][n0],     ah[0], bh[0], bh[1]);
                mma16816(acc[1][n0],     ah[1], bh[0], bh[1]);
                mma16816(acc[0][n0 + 1], ah[0], bh[2], bh[3]);
                mma16816(acc[1][n0 + 1], ah[1], bh[2], bh[3]);
            }
        }
    }

    // ---- epilogue: scale Q by eta, fp16, store to scratch --------------------
    const float eta = 1.44269504088896340736f * rsqrtf((float)CDIM);
    const size_t grow0 = (size_t)blockIdx.x * 128;
#pragma unroll
    for (int mt = 0; mt < 2; ++mt) {
#pragma unroll
        for (int ntl = 0; ntl < 12; ++ntl) {
            const int ntg = wn * 12 + ntl;
#pragma unroll
            for (int r = 0; r < 2; ++r) {
                float p0 = acc[mt][ntl][2 * r], p1 = acc[mt][ntl][2 * r + 1];
                if (ntg < 8) { p0 *= eta; p1 *= eta; }
                int row = (wm << 5) + (mt << 4) + g + (r << 3);
                size_t gi = (grow0 + row) * NDIM + (ntg << 3) + t2;
                *reinterpret_cast<uint32_t*>(&g_qkv[gi]) = pkh(p0, p1);
            }
        }
    }
}

// ============================================================================
// Kernel 2: balanced causal flash attention (fp16 single-chain).
// Warp w owns 16-row blocks {w, 15-w} -> exactly 5 block-units per warp.
// ============================================================================
#define AQ 0
#define AK 32768
#define AV 65536
#define ASMEM 98304

__global__ void __launch_bounds__(256, 1)
attn_kernel(float* __restrict__ out)
{
    extern __shared__ char sm[];
    const uint32_t smb = smem_u32(sm);
    const int tid = threadIdx.x, lane = tid & 31, w = tid >> 5;
    const int g = lane >> 2, t2 = (lane & 3) << 1;
    const size_t base = (size_t)blockIdx.x * TSEQ * NDIM;

    const int rbase0 = w << 4,  rbase1 = (15 - w) << 4;
    const int jmax0  = w >> 2,  jmax1  = (15 - w) >> 2;   // jmax1 >= jmax0

    // stage Q/K/V fp16 -> swizzled smem
    for (int sec = 0; sec < 3; ++sec) {
#pragma unroll
        for (int i = 0; i < 8; ++i) {
            int idx = tid + (i << 8);
            int row = idx >> 3, a = idx & 7;
            size_t gi = base + (size_t)row * NDIM + sec * 64 + (a << 3);
            uint4 h = *reinterpret_cast<const uint4*>(&g_qkv[gi]);
            *reinterpret_cast<uint4*>(sm + sec * 32768 + swz128(row, a << 4)) = h;
        }
    }
    __syncthreads();

    float O[2][8][4];
#pragma unroll
    for (int mt = 0; mt < 2; ++mt)
#pragma unroll
        for (int nt = 0; nt < 8; ++nt)
#pragma unroll
            for (int i = 0; i < 4; ++i) O[mt][nt][i] = 0.f;
    float mrow[2][2] = {{-1e30f, -1e30f}, {-1e30f, -1e30f}};
    float lrow[2][2] = {{0.f, 0.f}, {0.f, 0.f}};

    for (int jt = 0; jt <= jmax1; ++jt) {
        const bool act0 = (jt <= jmax0);
        float S[2][8][4];
#pragma unroll
        for (int mt = 0; mt < 2; ++mt)
#pragma unroll
            for (int nt = 0; nt < 8; ++nt)
#pragma unroll
                for (int i = 0; i < 4; ++i) S[mt][nt][i] = 0.f;

        // ---- S = Q K^T (single chain) ----------------------------------------
#pragma unroll
        for (int ks = 0; ks < 4; ++ks) {
            uint32_t qh[2][4];
            int abyte = ((ks << 1) + (lane >> 4)) << 4;
            int lrow16 = lane & 15;
            if (act0) ldsm4(qh[0], smb + AQ + swz128(rbase0 + lrow16, abyte));
            ldsm4(qh[1], smb + AQ + swz128(rbase1 + lrow16, abyte));
            int kr    = (jt << 6) + (lane & 7);
            int kbyte = ((ks << 1) + ((lane >> 3) & 1)) << 4;
#pragma unroll
            for (int nt = 0; nt < 8; ++nt) {
                uint32_t b0, b1;
                ldsm2(b0, b1, smb + AK + swz128(kr + (nt << 3), kbyte));
                if (act0) mma16816(S[0][nt], qh[0], b0, b1);
                mma16816(S[1][nt], qh[1], b0, b1);
            }
        }
        // ---- causal mask on each block's diagonal tile ------------------------
#pragma unroll
        for (int mt = 0; mt < 2; ++mt) {
            const int jm = (mt == 0) ? jmax0 : jmax1;
            const int rb = (mt == 0) ? rbase0 : rbase1;
            if (jt == jm) {
#pragma unroll
                for (int nt = 0; nt < 8; ++nt)
#pragma unroll
                    for (int r = 0; r < 2; ++r)
#pragma unroll
                        for (int cc = 0; cc < 2; ++cc) {
                            int col = (jt << 6) + (nt << 3) + t2 + cc;
                            int row = rb + g + (r << 3);
                            if (col > row) S[mt][nt][2 * r + cc] = -1e30f;
                        }
            }
        }
        // ---- online softmax (active blocks only) ------------------------------
#pragma unroll
        for (int mt = 0; mt < 2; ++mt) {
            if (mt == 0 && !act0) continue;
#pragma unroll
            for (int r = 0; r < 2; ++r) {
                float vmax = -1e30f;
#pragma unroll
                for (int nt = 0; nt < 8; ++nt)
                    vmax = fmaxf(vmax, fmaxf(S[mt][nt][2 * r], S[mt][nt][2 * r + 1]));
                vmax = fmaxf(vmax, __shfl_xor_sync(0xffffffffu, vmax, 1));
                vmax = fmaxf(vmax, __shfl_xor_sync(0xffffffffu, vmax, 2));
                float mnew  = fmaxf(mrow[mt][r], vmax);
                float alpha = ex2(mrow[mt][r] - mnew);
                mrow[mt][r] = mnew;
                float ls = 0.f;
#pragma unroll
                for (int nt = 0; nt < 8; ++nt) {
                    float p0 = ex2(S[mt][nt][2 * r]     - mnew);
                    float p1 = ex2(S[mt][nt][2 * r + 1] - mnew);
                    S[mt][nt][2 * r] = p0; S[mt][nt][2 * r + 1] = p1;
                    ls += p0 + p1;
                }
                lrow[mt][r] = lrow[mt][r] * alpha + ls;
#pragma unroll
                for (int nt = 0; nt < 8; ++nt) {
                    O[mt][nt][2 * r]     *= alpha;
                    O[mt][nt][2 * r + 1] *= alpha;
                }
            }
        }
        // ---- O += P V (single chain) -------------------------------------------
#pragma unroll
        for (int ks = 0; ks < 4; ++ks) {
            uint32_t ph[2][4];
#pragma unroll
            for (int mt = 0; mt < 2; ++mt) {
                if (mt == 0 && !act0) continue;
                ph[mt][0] = pkh(S[mt][2 * ks][0],     S[mt][2 * ks][1]);
                ph[mt][1] = pkh(S[mt][2 * ks][2],     S[mt][2 * ks][3]);
                ph[mt][2] = pkh(S[mt][2 * ks + 1][0], S[mt][2 * ks + 1][1]);
                ph[mt][3] = pkh(S[mt][2 * ks + 1][2], S[mt][2 * ks + 1][3]);
            }
            int vr = (jt << 6) + (ks << 4) + (lane & 15);
#pragma unroll
            for (int nt = 0; nt < 8; ++nt) {
                uint32_t b0, b1;
                ldsm2t(b0, b1, smb + AV + swz128(vr, nt << 4));
                if (act0) mma16816(O[0][nt], ph[0], b0, b1);
                mma16816(O[1][nt], ph[1], b0, b1);
            }
        }
    }

    // ---- finalize + store ------------------------------------------------------
#pragma unroll
    for (int mt = 0; mt < 2; ++mt) {
        const int rb = (mt == 0) ? rbase0 : rbase1;
#pragma unroll
        for (int r = 0; r < 2; ++r) {
            float lt = lrow[mt][r];
            lt += __shfl_xor_sync(0xffffffffu, lt, 1);
            lt += __shfl_xor_sync(0xffffffffu, lt, 2);
            float inv = __frcp_rn(lt);
            int row = rb + g + (r << 3);
            float* op = out + ((size_t)blockIdx.x * TSEQ + row) * HDIM;
#pragma unroll
            for (int nt = 0; nt < 8; ++nt) {
                float2 v = make_float2(O[mt][nt][2 * r] * inv, O[mt][nt][2 * r + 1] * inv);
                *reinterpret_cast<float2*>(op + (nt << 3) + t2) = v;
            }
        }
    }
}

// ---- launch -----------------------------------------------------------------
extern "C" void kernel_launch(void* const* d_in, const int* in_sizes, int n_in,
                              void* d_out, int out_size)
{
    const float* x  = (const float*)d_in[0];
    const float* Wq = (const float*)d_in[1];
    const float* Wk = (const float*)d_in[2];
    const float* Wv = (const float*)d_in[3];
    float* out = (float*)d_out;

    int B = in_sizes[0] / (TSEQ * CDIM);          // 1024
    int Mtiles = (B * TSEQ) / 128;                // 2048

    cudaFuncSetAttribute(proj_kernel, cudaFuncAttributeMaxDynamicSharedMemorySize, PSMEM);
    cudaFuncSetAttribute(attn_kernel, cudaFuncAttributeMaxDynamicSharedMemorySize, ASMEM);

    prep_w<<<(CDIM * NDIM + 255) / 256, 256>>>(Wq, Wk, Wv);
    proj_kernel<<<Mtiles, 256, PSMEM>>>(x);
    attn_kernel<<<B, 256, ASMEM>>>(out);
}

// round 13
// speedup vs baseline: 9.4233x; 1.2429x over previous
#include <cuda_runtime.h>
#include <cuda_fp16.h>
#include <math.h>
#include <stdint.h>

#define BATCH 1024
#define TSEQ  256
#define CDIM  384
#define HDIM  64
#define NDIM  192
#define KC    64

// ---- global scratch: pre-swizzled fp16 W ------------------------------------
__device__ __align__(16) __half gW[CDIM * NDIM];

// ---- helpers ----------------------------------------------------------------
__device__ __forceinline__ uint32_t smem_u32(const void* p) {
    uint32_t a;
    asm("{ .reg .u64 t; cvta.to.shared.u64 t, %1; cvt.u32.u64 %0, t; }" : "=r"(a) : "l"(p));
    return a;
}
// 128B-row tile swizzle (8 16B atoms per row)
__device__ __forceinline__ int swz128(int row, int byteoff) {
    return row * 128 + ((((byteoff >> 4) ^ row) & 7) << 4) + (byteoff & 15);
}
// W tile: 384B rows (24 atoms), swizzle within 8-atom groups
__device__ __forceinline__ int swzW(int k, int byteoff) {
    int atom = byteoff >> 4;
    return k * 384 + (((atom & ~7) | ((atom ^ k) & 7)) << 4) + (byteoff & 15);
}
__device__ __forceinline__ uint32_t pkh(float lo, float hi) {   // f16x2 {hi|lo}
    uint32_t r; asm("cvt.rn.f16x2.f32 %0, %1, %2;" : "=r"(r) : "f"(hi), "f"(lo)); return r;
}
__device__ __forceinline__ float ex2(float x) {
    float y; asm("ex2.approx.ftz.f32 %0, %1;" : "=f"(y) : "f"(x)); return y;
}
__device__ __forceinline__ void ldsm4(uint32_t* r, uint32_t a) {
    asm volatile("ldmatrix.sync.aligned.m8n8.x4.shared.b16 {%0,%1,%2,%3}, [%4];"
                 : "=r"(r[0]), "=r"(r[1]), "=r"(r[2]), "=r"(r[3]) : "r"(a));
}
__device__ __forceinline__ void ldsm4t(uint32_t* r, uint32_t a) {
    asm volatile("ldmatrix.sync.aligned.m8n8.x4.trans.shared.b16 {%0,%1,%2,%3}, [%4];"
                 : "=r"(r[0]), "=r"(r[1]), "=r"(r[2]), "=r"(r[3]) : "r"(a));
}
__device__ __forceinline__ void ldsm2(uint32_t& r0, uint32_t& r1, uint32_t a) {
    asm volatile("ldmatrix.sync.aligned.m8n8.x2.shared.b16 {%0,%1}, [%2];"
                 : "=r"(r0), "=r"(r1) : "r"(a));
}
__device__ __forceinline__ void ldsm2t(uint32_t& r0, uint32_t& r1, uint32_t a) {
    asm volatile("ldmatrix.sync.aligned.m8n8.x2.trans.shared.b16 {%0,%1}, [%2];"
                 : "=r"(r0), "=r"(r1) : "r"(a));
}
__device__ __forceinline__ void mma16816(float* c, const uint32_t* a,
                                         uint32_t b0, uint32_t b1) {
    asm volatile("mma.sync.aligned.m16n8k16.row.col.f32.f16.f16.f32 "
                 "{%0,%1,%2,%3}, {%4,%5,%6,%7}, {%8,%9}, {%0,%1,%2,%3};"
                 : "+f"(c[0]), "+f"(c[1]), "+f"(c[2]), "+f"(c[3])
                 : "r"(a[0]), "r"(a[1]), "r"(a[2]), "r"(a[3]), "r"(b0), "r"(b1));
}

// ============================================================================
// Kernel 0: pre-convert W -> fp16, pre-swizzled [384k x 192n] layout.
// ============================================================================
__global__ void prep_w(const float* __restrict__ Wq, const float* __restrict__ Wk,
                       const float* __restrict__ Wv) {
    int idx = blockIdx.x * 256 + threadIdx.x;      // over 384*192
    if (idx >= CDIM * NDIM) return;
    int k = idx / NDIM, n = idx % NDIM;
    const float* Wp = (n < 64) ? Wq : (n < 128) ? Wk : Wv;
    float v = Wp[k * HDIM + (n & 63)];
    *reinterpret_cast<__half*>(reinterpret_cast<char*>(gW) + swzW(k, 2 * n)) =
        __float2half_rn(v);
}

// ============================================================================
// Fused kernel: QKV projection (2 half-passes) + causal flash attention.
// grid = 1024 (one CTA per batch), 256 thr.
// smem: Q 32KB | K 32KB | V 32KB | X dbuf 2x16KB | W dbuf 2x24KB = 176KB
// ============================================================================
#define FQ 0
#define FK 32768
#define FV 65536
#define FX(buf) (98304  + (buf) * 16384)
#define FW(buf) (131072 + (buf) * 24576)
#define FSMEM 180224

__global__ void __launch_bounds__(256, 1)
head_kernel(const float* __restrict__ x, float* __restrict__ out)
{
    extern __shared__ char sm[];
    const uint32_t smb = smem_u32(sm);
    const int tid = threadIdx.x, lane = tid & 31, w = tid >> 5;
    const int wm = w & 3, wn = w >> 2;
    const int g = lane >> 2, t2 = (lane & 3) << 1;
    const char* gw = reinterpret_cast<const char*>(gW);
    const float eta = 1.44269504088896340736f * rsqrtf((float)CDIM);

    // ===================== Phase 1: QKV -> smem (2 half-passes) ==============
    for (int half = 0; half < 2; ++half) {
        const int rhalf = half << 7;                       // 0 or 128
        const float* gx = x + ((size_t)blockIdx.x * TSEQ + rhalf) * CDIM;

        float acc[2][12][4];
#pragma unroll
        for (int mt = 0; mt < 2; ++mt)
#pragma unroll
            for (int nt = 0; nt < 12; ++nt)
#pragma unroll
                for (int i = 0; i < 4; ++i) acc[mt][nt][i] = 0.f;

        // prefetch X chunk 0 of this half
        float4 xp[8];
#pragma unroll
        for (int i = 0; i < 8; ++i) {
            int idx = tid + (i << 8);
            xp[i] = *reinterpret_cast<const float4*>(
                gx + (idx >> 4) * CDIM + ((idx & 15) << 2));
        }

        for (int ch = 0; ch < 6; ++ch) {
            const int buf = ch & 1;
            // ---- store prefetched X chunk (f32 -> fp16, swizzled) ------------
#pragma unroll
            for (int i = 0; i < 8; ++i) {
                int idx = tid + (i << 8);
                int row = idx >> 4, f4 = idx & 15;
                float4 v = xp[i];
                *reinterpret_cast<uint2*>(sm + FX(buf) + swz128(row, f4 << 3)) =
                    make_uint2(pkh(v.x, v.y), pkh(v.z, v.w));
            }
            // ---- stage W chunk (raw uint4 copy of preconverted fp16) ---------
            {
                const int slab = ch * 24576;
#pragma unroll
                for (int i = 0; i < 6; ++i) {
                    int boff = (tid + (i << 8)) << 4;
                    *reinterpret_cast<uint4*>(sm + FW(buf) + boff) =
                        *reinterpret_cast<const uint4*>(gw + slab + boff);
                }
            }
            __syncthreads();
            // ---- prefetch next X chunk ---------------------------------------
            if (ch < 5) {
                const int kc = (ch + 1) * KC;
#pragma unroll
                for (int i = 0; i < 8; ++i) {
                    int idx = tid + (i << 8);
                    xp[i] = *reinterpret_cast<const float4*>(
                        gx + (idx >> 4) * CDIM + kc + ((idx & 15) << 2));
                }
            }
            // ---- mma: single fp16 chain ---------------------------------------
#pragma unroll
            for (int ks = 0; ks < 4; ++ks) {
                uint32_t ah[2][4];
                int arow  = (wm << 5) + (lane & 15);
                int abyte = ((ks << 1) + (lane >> 4)) << 4;
                ldsm4(ah[0], smb + FX(buf) + swz128(arow,      abyte));
                ldsm4(ah[1], smb + FX(buf) + swz128(arow + 16, abyte));
                int krow = (ks << 4) + (lane & 15);
#pragma unroll
                for (int j = 0; j < 6; ++j) {
                    const int n0 = 2 * j;
                    const int ntg = wn * 12 + n0;
                    uint32_t bh[4];
                    ldsm4t(bh, smb + FW(buf) + swzW(krow, (ntg + (lane >> 4)) << 4));
                    mma16816(acc[0][n0],     ah[0], bh[0], bh[1]);
                    mma16816(acc[1][n0],     ah[1], bh[0], bh[1]);
                    mma16816(acc[0][n0 + 1], ah[0], bh[2], bh[3]);
                    mma16816(acc[1][n0 + 1], ah[1], bh[2], bh[3]);
                }
            }
        }

        // ---- epilogue: Q scaled by eta; write fp16 into attn smem layout -----
#pragma unroll
        for (int mt = 0; mt < 2; ++mt) {
#pragma unroll
            for (int ntl = 0; ntl < 12; ++ntl) {
                const int ntg = wn * 12 + ntl;
#pragma unroll
                for (int r = 0; r < 2; ++r) {
                    float p0 = acc[mt][ntl][2 * r], p1 = acc[mt][ntl][2 * r + 1];
                    if (ntg < 8) { p0 *= eta; p1 *= eta; }
                    int row = rhalf + (wm << 5) + (mt << 4) + g + (r << 3);
                    int sec = ntg >> 3;                    // 0=Q 1=K 2=V
                    int off = swz128(row, ((ntg & 7) << 4) + (t2 << 1));
                    *reinterpret_cast<uint32_t*>(sm + sec * 32768 + off) = pkh(p0, p1);
                }
            }
        }
    }
    __syncthreads();   // QKV smem complete, staging buffers now dead

    // ===================== Phase 2: balanced causal flash attention ==========
    const int rbase0 = w << 4,  rbase1 = (15 - w) << 4;
    const int jmax0  = w >> 2,  jmax1  = (15 - w) >> 2;    // jmax1 >= jmax0

    float O[2][8][4];
#pragma unroll
    for (int mt = 0; mt < 2; ++mt)
#pragma unroll
        for (int nt = 0; nt < 8; ++nt)
#pragma unroll
            for (int i = 0; i < 4; ++i) O[mt][nt][i] = 0.f;
    float mrow[2][2] = {{-1e30f, -1e30f}, {-1e30f, -1e30f}};
    float lrow[2][2] = {{0.f, 0.f}, {0.f, 0.f}};

    for (int jt = 0; jt <= jmax1; ++jt) {
        const bool act0 = (jt <= jmax0);
        float S[2][8][4];
#pragma unroll
        for (int mt = 0; mt < 2; ++mt)
#pragma unroll
            for (int nt = 0; nt < 8; ++nt)
#pragma unroll
                for (int i = 0; i < 4; ++i) S[mt][nt][i] = 0.f;

        // ---- S = Q K^T ---------------------------------------------------------
#pragma unroll
        for (int ks = 0; ks < 4; ++ks) {
            uint32_t qh[2][4];
            int abyte = ((ks << 1) + (lane >> 4)) << 4;
            int lrow16 = lane & 15;
            if (act0) ldsm4(qh[0], smb + FQ + swz128(rbase0 + lrow16, abyte));
            ldsm4(qh[1], smb + FQ + swz128(rbase1 + lrow16, abyte));
            int kr    = (jt << 6) + (lane & 7);
            int kbyte = ((ks << 1) + ((lane >> 3) & 1)) << 4;
#pragma unroll
            for (int nt = 0; nt < 8; ++nt) {
                uint32_t b0, b1;
                ldsm2(b0, b1, smb + FK + swz128(kr + (nt << 3), kbyte));
                if (act0) mma16816(S[0][nt], qh[0], b0, b1);
                mma16816(S[1][nt], qh[1], b0, b1);
            }
        }
        // ---- causal mask on each block's diagonal tile ---------------------------
#pragma unroll
        for (int mt = 0; mt < 2; ++mt) {
            const int jm = (mt == 0) ? jmax0 : jmax1;
            const int rb = (mt == 0) ? rbase0 : rbase1;
            if (jt == jm) {
#pragma unroll
                for (int nt = 0; nt < 8; ++nt)
#pragma unroll
                    for (int r = 0; r < 2; ++r)
#pragma unroll
                        for (int cc = 0; cc < 2; ++cc) {
                            int col = (jt << 6) + (nt << 3) + t2 + cc;
                            int row = rb + g + (r << 3);
                            if (col > row) S[mt][nt][2 * r + cc] = -1e30f;
                        }
            }
        }
        // ---- online softmax (active blocks only) ---------------------------------
#pragma unroll
        for (int mt = 0; mt < 2; ++mt) {
            if (mt == 0 && !act0) continue;
#pragma unroll
            for (int r = 0; r < 2; ++r) {
                float vmax = -1e30f;
#pragma unroll
                for (int nt = 0; nt < 8; ++nt)
                    vmax = fmaxf(vmax, fmaxf(S[mt][nt][2 * r], S[mt][nt][2 * r + 1]));
                vmax = fmaxf(vmax, __shfl_xor_sync(0xffffffffu, vmax, 1));
                vmax = fmaxf(vmax, __shfl_xor_sync(0xffffffffu, vmax, 2));
                float mnew  = fmaxf(mrow[mt][r], vmax);
                float alpha = ex2(mrow[mt][r] - mnew);
                mrow[mt][r] = mnew;
                float ls = 0.f;
#pragma unroll
                for (int nt = 0; nt < 8; ++nt) {
                    float p0 = ex2(S[mt][nt][2 * r]     - mnew);
                    float p1 = ex2(S[mt][nt][2 * r + 1] - mnew);
                    S[mt][nt][2 * r] = p0; S[mt][nt][2 * r + 1] = p1;
                    ls += p0 + p1;
                }
                lrow[mt][r] = lrow[mt][r] * alpha + ls;
#pragma unroll
                for (int nt = 0; nt < 8; ++nt) {
                    O[mt][nt][2 * r]     *= alpha;
                    O[mt][nt][2 * r + 1] *= alpha;
                }
            }
        }
        // ---- O += P V (active blocks only) ----------------------------------------
#pragma unroll
        for (int ks = 0; ks < 4; ++ks) {
            uint32_t ph[2][4];
#pragma unroll
            for (int mt = 0; mt < 2; ++mt) {
                if (mt == 0 && !act0) continue;
                ph[mt][0] = pkh(S[mt][2 * ks][0],     S[mt][2 * ks][1]);
                ph[mt][1] = pkh(S[mt][2 * ks][2],     S[mt][2 * ks][3]);
                ph[mt][2] = pkh(S[mt][2 * ks + 1][0], S[mt][2 * ks + 1][1]);
                ph[mt][3] = pkh(S[mt][2 * ks + 1][2], S[mt][2 * ks + 1][3]);
            }
            int vr = (jt << 6) + (ks << 4) + (lane & 15);
#pragma unroll
            for (int nt = 0; nt < 8; ++nt) {
                uint32_t b0, b1;
                ldsm2t(b0, b1, smb + FV + swz128(vr, nt << 4));
                if (act0) mma16816(O[0][nt], ph[0], b0, b1);
                mma16816(O[1][nt], ph[1], b0, b1);
            }
        }
    }

    // ---- finalize + store --------------------------------------------------------
#pragma unroll
    for (int mt = 0; mt < 2; ++mt) {
        const int rb = (mt == 0) ? rbase0 : rbase1;
#pragma unroll
        for (int r = 0; r < 2; ++r) {
            float lt = lrow[mt][r];
            lt += __shfl_xor_sync(0xffffffffu, lt, 1);
            lt += __shfl_xor_sync(0xffffffffu, lt, 2);
            float inv = __frcp_rn(lt);
            int row = rb + g + (r << 3);
            float* op = out + ((size_t)blockIdx.x * TSEQ + row) * HDIM;
#pragma unroll
            for (int nt = 0; nt < 8; ++nt) {
                float2 v = make_float2(O[mt][nt][2 * r] * inv, O[mt][nt][2 * r + 1] * inv);
                *reinterpret_cast<float2*>(op + (nt << 3) + t2) = v;
            }
        }
    }
}

// ---- launch -----------------------------------------------------------------
extern "C" void kernel_launch(void* const* d_in, const int* in_sizes, int n_in,
                              void* d_out, int out_size)
{
    const float* x  = (const float*)d_in[0];
    const float* Wq = (const float*)d_in[1];
    const float* Wk = (const float*)d_in[2];
    const float* Wv = (const float*)d_in[3];
    float* out = (float*)d_out;

    int B = in_sizes[0] / (TSEQ * CDIM);          // 1024

    cudaFuncSetAttribute(head_kernel, cudaFuncAttributeMaxDynamicSharedMemorySize, FSMEM);

    prep_w<<<(CDIM * NDIM + 255) / 256, 256>>>(Wq, Wk, Wv);
    head_kernel<<<B, 256, FSMEM>>>(x, out);
}